// round 10
// baseline (speedup 1.0000x reference)
#include <cuda_runtime.h>
#include <math.h>
#include <stdint.h>

#define T_TOK 2048
#define DIM   2048
#define NEXP  8
#define EW    (NEXP * DIM * DIM)
#define SW    (DIM * DIM)
#define EW4   (EW / 4)
#define SW4   (SW / 4)

// ---------------- scratch (device globals) ----------------------------------
__device__ uint16_t g_gw_h[EW], g_gw_l[EW];
__device__ uint16_t g_uw_h[EW], g_uw_l[EW];
__device__ uint16_t g_dw_h[EW], g_dw_l[EW];
__device__ uint16_t g_sg_h[SW], g_sg_l[SW];
__device__ uint16_t g_su_h[SW], g_su_l[SW];
__device__ uint16_t g_sd_h[SW], g_sd_l[SW];
__device__ uint16_t g_x_h [SW], g_x_l [SW];
__device__ uint16_t g_xs_h[SW], g_xs_l[SW];
__device__ uint16_t g_Hs_h[SW], g_Hs_l[SW];
__device__ uint16_t g_Hr_h[SW], g_Hr_l[SW];
__device__ float    g_R[T_TOK * DIM];
__device__ int g_off[NEXP + 1];
__device__ int g_eidx[T_TOK], g_perm[T_TOK];
__device__ int g_tile_e[32], g_tile_m[32], g_ntiles;

// ---------------- helpers ----------------------------------------------------
__device__ __forceinline__ uint32_t smem_u32(const void* p) {
  uint32_t a;
  asm("{ .reg .u64 t; cvta.to.shared.u64 t, %1; cvt.u32.u64 %0, t; }" : "=r"(a) : "l"(p));
  return a;
}
__device__ __forceinline__ void cp16(uint32_t dst, const void* src) {
  asm volatile("cp.async.cg.shared.global [%0], [%1], 16;" :: "r"(dst), "l"(src));
}
__device__ __forceinline__ uint32_t pack_hi(float x, float y) {
  return __byte_perm(__float_as_uint(x), __float_as_uint(y), 0x7632);
}
__device__ __forceinline__ uint32_t pack_lo(float x, float y) {
  float lx = x - __uint_as_float(__float_as_uint(x) & 0xFFFF0000u);
  float ly = y - __uint_as_float(__float_as_uint(y) & 0xFFFF0000u);
  uint32_t r;
  asm("cvt.rn.bf16x2.f32 %0, %1, %2;" : "=r"(r) : "f"(ly), "f"(lx));
  return r;
}
__device__ __forceinline__ void mma16816(float* d, const uint32_t* a,
                                         uint32_t b0, uint32_t b1) {
  asm volatile("mma.sync.aligned.m16n8k16.row.col.f32.bf16.bf16.f32 "
               "{%0,%1,%2,%3}, {%4,%5,%6,%7}, {%8,%9}, {%0,%1,%2,%3};"
               : "+f"(d[0]), "+f"(d[1]), "+f"(d[2]), "+f"(d[3])
               : "r"(a[0]), "r"(a[1]), "r"(a[2]), "r"(a[3]), "r"(b0), "r"(b1));
}
#define LDSM4(r, a)                                                            \
  asm volatile("ldmatrix.sync.aligned.m8n8.x4.shared.b16 {%0,%1,%2,%3}, [%4];" \
    : "=r"((r)[0]), "=r"((r)[1]), "=r"((r)[2]), "=r"((r)[3]) : "r"(a))
#define LDSM4T(r, a)                                                           \
  asm volatile("ldmatrix.sync.aligned.m8n8.x4.trans.shared.b16 {%0,%1,%2,%3}, [%4];" \
    : "=r"((r)[0]), "=r"((r)[1]), "=r"((r)[2]), "=r"((r)[3]) : "r"(a))

// ---------------- setup kernels ----------------------------------------------
__global__ void router_kernel(const float* __restrict__ x,
                              const float* __restrict__ rw) {
  int tok  = (blockIdx.x * blockDim.x + threadIdx.x) >> 5;
  int lane = threadIdx.x & 31;
  if (tok >= T_TOK) return;
  const float* xr = x + (size_t)tok * DIM;
  float acc[NEXP];
#pragma unroll
  for (int e = 0; e < NEXP; e++) acc[e] = 0.f;
  for (int k = lane; k < DIM; k += 32) {
    float xv = xr[k];
    const float4* w4 = reinterpret_cast<const float4*>(rw + (size_t)k * NEXP);
    float4 w0 = w4[0], w1 = w4[1];
    acc[0] = fmaf(xv, w0.x, acc[0]); acc[1] = fmaf(xv, w0.y, acc[1]);
    acc[2] = fmaf(xv, w0.z, acc[2]); acc[3] = fmaf(xv, w0.w, acc[3]);
    acc[4] = fmaf(xv, w1.x, acc[4]); acc[5] = fmaf(xv, w1.y, acc[5]);
    acc[6] = fmaf(xv, w1.z, acc[6]); acc[7] = fmaf(xv, w1.w, acc[7]);
  }
#pragma unroll
  for (int o = 16; o > 0; o >>= 1)
#pragma unroll
    for (int e = 0; e < NEXP; e++)
      acc[e] += __shfl_down_sync(0xffffffffu, acc[e], o);
  float sc = 0.f;
  if (lane == 0) {
    float mx = acc[0]; int im = 0;
#pragma unroll
    for (int e = 1; e < NEXP; e++) if (acc[e] > mx) { mx = acc[e]; im = e; }
    sc = 1.f / (1.f + expf(-mx));
    g_eidx[tok] = im;
  }
  sc = __shfl_sync(0xffffffffu, sc, 0);
  const float4* x4 = reinterpret_cast<const float4*>(xr);
  uint2* xh = reinterpret_cast<uint2*>(g_x_h)  + (size_t)tok * (DIM / 4);
  uint2* xl = reinterpret_cast<uint2*>(g_x_l)  + (size_t)tok * (DIM / 4);
  uint2* sh = reinterpret_cast<uint2*>(g_xs_h) + (size_t)tok * (DIM / 4);
  uint2* sl = reinterpret_cast<uint2*>(g_xs_l) + (size_t)tok * (DIM / 4);
  for (int k = lane; k < DIM / 4; k += 32) {
    float4 v = x4[k];
    uint2 h, l;
    h.x = pack_hi(v.x, v.y); h.y = pack_hi(v.z, v.w);
    l.x = pack_lo(v.x, v.y); l.y = pack_lo(v.z, v.w);
    xh[k] = h; xl[k] = l;
    float4 s = make_float4(v.x * sc, v.y * sc, v.z * sc, v.w * sc);
    h.x = pack_hi(s.x, s.y); h.y = pack_hi(s.z, s.w);
    l.x = pack_lo(s.x, s.y); l.y = pack_lo(s.z, s.w);
    sh[k] = h; sl[k] = l;
  }
}

__global__ void plan_kernel() {
  __shared__ int cnt[NEXP], cur[NEXP];
  int t = threadIdx.x;
  if (t < NEXP) cnt[t] = 0;
  __syncthreads();
  for (int i = t; i < T_TOK; i += 256) atomicAdd(&cnt[g_eidx[i]], 1);
  __syncthreads();
  if (t == 0) {
    int o = 0, nt = 0;
    for (int e = 0; e < NEXP; e++) {
      g_off[e] = o; cur[e] = o;
      int c = cnt[e];
      for (int m = 0; m < c; m += 128) { g_tile_e[nt] = e; g_tile_m[nt] = o + m; nt++; }
      o += c;
    }
    g_off[NEXP] = o;
    g_ntiles = nt;
  }
  __syncthreads();
  for (int i = t; i < T_TOK; i += 256) {
    int e = g_eidx[i];
    int p = atomicAdd(&cur[e], 1);
    g_perm[p] = i;
  }
}

__global__ void split_all_kernel(const float4* __restrict__ gw, const float4* __restrict__ uw,
                                 const float4* __restrict__ dw, const float4* __restrict__ sg,
                                 const float4* __restrict__ su, const float4* __restrict__ sd) {
  int i = blockIdx.x * blockDim.x + threadIdx.x;
  const float4* src; uint2 *hi, *lo; int j;
  if      (i < EW4)            { src = gw; hi = (uint2*)g_gw_h; lo = (uint2*)g_gw_l; j = i; }
  else if (i < 2 * EW4)        { src = uw; hi = (uint2*)g_uw_h; lo = (uint2*)g_uw_l; j = i - EW4; }
  else if (i < 3 * EW4)        { src = dw; hi = (uint2*)g_dw_h; lo = (uint2*)g_dw_l; j = i - 2 * EW4; }
  else if (i < 3 * EW4 + SW4)  { src = sg; hi = (uint2*)g_sg_h; lo = (uint2*)g_sg_l; j = i - 3 * EW4; }
  else if (i < 3 * EW4 + 2 * SW4) { src = su; hi = (uint2*)g_su_h; lo = (uint2*)g_su_l; j = i - 3 * EW4 - SW4; }
  else if (i < 3 * EW4 + 3 * SW4) { src = sd; hi = (uint2*)g_sd_h; lo = (uint2*)g_sd_l; j = i - 3 * EW4 - 2 * SW4; }
  else return;
  float4 v = src[j];
  uint2 h, l;
  h.x = pack_hi(v.x, v.y); h.y = pack_hi(v.z, v.w);
  l.x = pack_lo(v.x, v.y); l.y = pack_lo(v.z, v.w);
  hi[j] = h; lo[j] = l;
}

__global__ void scatter_add_kernel(float4* __restrict__ out) {
  int i = blockIdx.x * blockDim.x + threadIdx.x;
  if (i >= T_TOK * DIM / 4) return;
  int p = i >> 9;
  int j = i & 511;
  int t = g_perm[p];
  const float4* R4 = reinterpret_cast<const float4*>(g_R);
  float4 r = R4[i];
  float4 o = out[(size_t)t * 512 + j];
  o.x += r.x; o.y += r.y; o.z += r.z; o.w += r.w;
  out[(size_t)t * 512 + j] = o;
}

// ---------------- stage1: fused gate/up GEMM, tile 128x64, 3-stage ----------
#define BK      32
#define NSTG    3
#define S1_LDB  144
#define S1_GH   18432
#define S1_GL   23040
#define S1_UH   27648
#define S1_UL   32256
#define S1_STG  36864
#define S1_SMEM (NSTG * S1_STG)
#define NCHUNK  (DIM / BK)

__device__ __forceinline__ void gemm1_core(
    const uint16_t* __restrict__ Ah, const uint16_t* __restrict__ Al,
    const uint16_t* __restrict__ Gh, const uint16_t* __restrict__ Gl,
    const uint16_t* __restrict__ Uh, const uint16_t* __restrict__ Ul,
    uint16_t* __restrict__ Hh, uint16_t* __restrict__ Hl,
    int m0, int mEnd, int n0, const int* __restrict__ perm, int gather) {
  extern __shared__ char smc[];
  const uint32_t smu = smem_u32(smc);
  const int t = threadIdx.x;
  const int lane = t & 31;
  const int wid  = t >> 5;
  const int wm = wid >> 1;
  const int wn = wid & 1;
  const int rsel = lane & 15;
  const int csel = lane >> 4;

  const int am = t >> 1, ahalf = t & 1;
  const int ga = m0 + am;
  const bool av = ga < mEnd;
  const int arow = gather ? (av ? perm[ga] : 0) : (av ? ga : 0);
  const uint16_t* aSrcH = Ah + (size_t)arow * DIM + ahalf * 16;
  const uint16_t* aSrcL = Al + (size_t)arow * DIM + ahalf * 16;
  const uint32_t dA = smu + (uint32_t)(am * 144 + ahalf * 32);
  const int brow = t >> 3, bseg = t & 7;
  const size_t bOff = (size_t)brow * DIM + n0 + bseg * 8;
  const uint32_t dB = smu + (uint32_t)(brow * S1_LDB + bseg * 16);

  float accG[2][4][4], accU[2][4][4];
#pragma unroll
  for (int i = 0; i < 2; i++)
#pragma unroll
    for (int j = 0; j < 4; j++)
#pragma unroll
      for (int q = 0; q < 4; q++) { accG[i][j][q] = 0.f; accU[i][j][q] = 0.f; }

  auto fill = [&](int st, int c) {
    const int k0 = c * BK;
    const uint32_t sb = (uint32_t)st * S1_STG;
    cp16(dA + sb,      aSrcH + k0);
    cp16(dA + sb + 16, aSrcH + k0 + 8);
    cp16(dA + sb + 64, aSrcL + k0);
    cp16(dA + sb + 80, aSrcL + k0 + 8);
    const size_t bk = bOff + (size_t)k0 * DIM;
    cp16(dB + sb + S1_GH, Gh + bk);
    cp16(dB + sb + S1_GL, Gl + bk);
    cp16(dB + sb + S1_UH, Uh + bk);
    cp16(dB + sb + S1_UL, Ul + bk);
  };

#pragma unroll
  for (int s = 0; s < NSTG - 1; s++) {
    fill(s, s);
    asm volatile("cp.async.commit_group;" ::: "memory");
  }

  for (int c = 0; c < NCHUNK; c++) {
    asm volatile("cp.async.wait_group %0;" :: "n"(NSTG - 2) : "memory");
    __syncthreads();
    if (c + NSTG - 1 < NCHUNK) fill((c + NSTG - 1) % NSTG, c + NSTG - 1);
    asm volatile("cp.async.commit_group;" ::: "memory");

    const uint32_t stg = smu + (uint32_t)((c % NSTG) * S1_STG);
#pragma unroll
    for (int ks = 0; ks < 2; ks++) {
      uint32_t ah[2][4], al[2][4];
#pragma unroll
      for (int mt = 0; mt < 2; mt++) {
        uint32_t ra = stg + (uint32_t)((wm * 32 + mt * 16 + rsel) * 144 +
                                       ks * 32 + csel * 16);
        LDSM4(ah[mt], ra);
        LDSM4(al[mt], ra + 64);
      }
#pragma unroll
      for (int np = 0; np < 2; np++) {
        uint32_t rb = stg + (uint32_t)((ks * 16 + rsel) * S1_LDB +
                                       (wn * 32 + np * 16 + csel * 8) * 2);
        const int f0 = np * 2, f1 = np * 2 + 1;
        uint32_t gh[4], uh[4];
        LDSM4T(gh, rb + S1_GH);
        LDSM4T(uh, rb + S1_UH);
        // term hh (8 independent accumulators)
        mma16816(accG[0][f0], ah[0], gh[0], gh[1]);
        mma16816(accG[1][f0], ah[1], gh[0], gh[1]);
        mma16816(accG[0][f1], ah[0], gh[2], gh[3]);
        mma16816(accG[1][f1], ah[1], gh[2], gh[3]);
        mma16816(accU[0][f0], ah[0], uh[0], uh[1]);
        mma16816(accU[1][f0], ah[1], uh[0], uh[1]);
        mma16816(accU[0][f1], ah[0], uh[2], uh[3]);
        mma16816(accU[1][f1], ah[1], uh[2], uh[3]);
        // lo fragments loaded after hh MMAs are in flight
        uint32_t gl[4], ul[4];
        LDSM4T(gl, rb + S1_GL);
        LDSM4T(ul, rb + S1_UL);
        // term hl
        mma16816(accG[0][f0], ah[0], gl[0], gl[1]);
        mma16816(accG[1][f0], ah[1], gl[0], gl[1]);
        mma16816(accG[0][f1], ah[0], gl[2], gl[3]);
        mma16816(accG[1][f1], ah[1], gl[2], gl[3]);
        mma16816(accU[0][f0], ah[0], ul[0], ul[1]);
        mma16816(accU[1][f0], ah[1], ul[0], ul[1]);
        mma16816(accU[0][f1], ah[0], ul[2], ul[3]);
        mma16816(accU[1][f1], ah[1], ul[2], ul[3]);
        // term lh
        mma16816(accG[0][f0], al[0], gh[0], gh[1]);
        mma16816(accG[1][f0], al[1], gh[0], gh[1]);
        mma16816(accG[0][f1], al[0], gh[2], gh[3]);
        mma16816(accG[1][f1], al[1], gh[2], gh[3]);
        mma16816(accU[0][f0], al[0], uh[0], uh[1]);
        mma16816(accU[1][f0], al[1], uh[0], uh[1]);
        mma16816(accU[0][f1], al[0], uh[2], uh[3]);
        mma16816(accU[1][f1], al[1], uh[2], uh[3]);
      }
    }
  }

#pragma unroll
  for (int mt = 0; mt < 2; mt++) {
#pragma unroll
    for (int h = 0; h < 2; h++) {
      const int row = m0 + wm * 32 + mt * 16 + (lane >> 2) + h * 8;
      if (row >= mEnd) continue;
      const int colb = n0 + wn * 32 + (lane & 3) * 2;
      uint16_t* hpH = Hh + (size_t)row * DIM + colb;
      uint16_t* hpL = Hl + (size_t)row * DIM + colb;
#pragma unroll
      for (int nf = 0; nf < 4; nf++) {
        float g0 = accG[mt][nf][h * 2],     u0 = accU[mt][nf][h * 2];
        float g1 = accG[mt][nf][h * 2 + 1], u1 = accU[mt][nf][h * 2 + 1];
        float h0 = g0 / (1.f + expf(-g0)) * u0;
        float h1 = g1 / (1.f + expf(-g1)) * u1;
        *reinterpret_cast<uint32_t*>(hpH + nf * 8) = pack_hi(h0, h1);
        *reinterpret_cast<uint32_t*>(hpL + nf * 8) = pack_lo(h0, h1);
      }
    }
  }
}

// ---------------- stage2: down GEMM, tile 128x64, 3-stage --------------------
#define S2_LDB  144
#define S2_BH   18432
#define S2_BL   23040
#define S2_STG  27648
#define S2_SMEM (NSTG * S2_STG)

__device__ __forceinline__ void gemm2_core(
    const uint16_t* __restrict__ Ah, const uint16_t* __restrict__ Al,
    const uint16_t* __restrict__ Bh, const uint16_t* __restrict__ Bl,
    float* __restrict__ C, int m0, int mEnd, int n0) {
  extern __shared__ char smc[];
  const uint32_t smu = smem_u32(smc);
  const int t = threadIdx.x;
  const int lane = t & 31;
  const int wid  = t >> 5;
  const int wm = wid >> 1;
  const int wn = wid & 1;
  const int rsel = lane & 15;
  const int csel = lane >> 4;

  const int am = t >> 1, ahalf = t & 1;
  const int ga = m0 + am;
  const bool av = ga < mEnd;
  const int arow = av ? ga : 0;
  const uint16_t* aSrcH = Ah + (size_t)arow * DIM + ahalf * 16;
  const uint16_t* aSrcL = Al + (size_t)arow * DIM + ahalf * 16;
  const uint32_t dA = smu + (uint32_t)(am * 144 + ahalf * 32);
  const int brow = t >> 3, bseg = t & 7;
  const size_t bOff = (size_t)brow * DIM + n0 + bseg * 8;
  const uint32_t dB = smu + (uint32_t)(brow * S2_LDB + bseg * 16);

  float acc[2][4][4];
#pragma unroll
  for (int i = 0; i < 2; i++)
#pragma unroll
    for (int j = 0; j < 4; j++)
#pragma unroll
      for (int q = 0; q < 4; q++) acc[i][j][q] = 0.f;

  auto fill = [&](int st, int c) {
    const int k0 = c * BK;
    const uint32_t sb = (uint32_t)st * S2_STG;
    cp16(dA + sb,      aSrcH + k0);
    cp16(dA + sb + 16, aSrcH + k0 + 8);
    cp16(dA + sb + 64, aSrcL + k0);
    cp16(dA + sb + 80, aSrcL + k0 + 8);
    const size_t bk = bOff + (size_t)k0 * DIM;
    cp16(dB + sb + S2_BH, Bh + bk);
    cp16(dB + sb + S2_BL, Bl + bk);
  };

#pragma unroll
  for (int s = 0; s < NSTG - 1; s++) {
    fill(s, s);
    asm volatile("cp.async.commit_group;" ::: "memory");
  }

  for (int c = 0; c < NCHUNK; c++) {
    asm volatile("cp.async.wait_group %0;" :: "n"(NSTG - 2) : "memory");
    __syncthreads();
    if (c + NSTG - 1 < NCHUNK) fill((c + NSTG - 1) % NSTG, c + NSTG - 1);
    asm volatile("cp.async.commit_group;" ::: "memory");

    const uint32_t stg = smu + (uint32_t)((c % NSTG) * S2_STG);
#pragma unroll
    for (int ks = 0; ks < 2; ks++) {
      uint32_t ah[2][4], al[2][4];
#pragma unroll
      for (int mt = 0; mt < 2; mt++) {
        uint32_t ra = stg + (uint32_t)((wm * 32 + mt * 16 + rsel) * 144 +
                                       ks * 32 + csel * 16);
        LDSM4(ah[mt], ra);
        LDSM4(al[mt], ra + 64);
      }
      uint32_t rb = stg + (uint32_t)((ks * 16 + rsel) * S2_LDB +
                                     (wn * 32 + csel * 8) * 2);
      uint32_t bh0[4], bh1[4];
      LDSM4T(bh0, rb + S2_BH);
      LDSM4T(bh1, rb + S2_BH + 32);
      // term hh (8 independent accumulators)
      mma16816(acc[0][0], ah[0], bh0[0], bh0[1]);
      mma16816(acc[1][0], ah[1], bh0[0], bh0[1]);
      mma16816(acc[0][1], ah[0], bh0[2], bh0[3]);
      mma16816(acc[1][1], ah[1], bh0[2], bh0[3]);
      mma16816(acc[0][2], ah[0], bh1[0], bh1[1]);
      mma16816(acc[1][2], ah[1], bh1[0], bh1[1]);
      mma16816(acc[0][3], ah[0], bh1[2], bh1[3]);
      mma16816(acc[1][3], ah[1], bh1[2], bh1[3]);
      // lo fragments loaded after hh MMAs are in flight
      uint32_t bl0[4], bl1[4];
      LDSM4T(bl0, rb + S2_BL);
      LDSM4T(bl1, rb + S2_BL + 32);
      // term hl
      mma16816(acc[0][0], ah[0], bl0[0], bl0[1]);
      mma16816(acc[1][0], ah[1], bl0[0], bl0[1]);
      mma16816(acc[0][1], ah[0], bl0[2], bl0[3]);
      mma16816(acc[1][1], ah[1], bl0[2], bl0[3]);
      mma16816(acc[0][2], ah[0], bl1[0], bl1[1]);
      mma16816(acc[1][2], ah[1], bl1[0], bl1[1]);
      mma16816(acc[0][3], ah[0], bl1[2], bl1[3]);
      mma16816(acc[1][3], ah[1], bl1[2], bl1[3]);
      // term lh
      mma16816(acc[0][0], al[0], bh0[0], bh0[1]);
      mma16816(acc[1][0], al[1], bh0[0], bh0[1]);
      mma16816(acc[0][1], al[0], bh0[2], bh0[3]);
      mma16816(acc[1][1], al[1], bh0[2], bh0[3]);
      mma16816(acc[0][2], al[0], bh1[0], bh1[1]);
      mma16816(acc[1][2], al[1], bh1[0], bh1[1]);
      mma16816(acc[0][3], al[0], bh1[2], bh1[3]);
      mma16816(acc[1][3], al[1], bh1[2], bh1[3]);
    }
  }

#pragma unroll
  for (int mt = 0; mt < 2; mt++) {
#pragma unroll
    for (int h = 0; h < 2; h++) {
      const int row = m0 + wm * 32 + mt * 16 + (lane >> 2) + h * 8;
      if (row >= mEnd) continue;
      float* cp = C + (size_t)row * DIM + n0 + wn * 32 + (lane & 3) * 2;
#pragma unroll
      for (int nf = 0; nf < 4; nf++) {
        float2 v = make_float2(acc[mt][nf][h * 2], acc[mt][nf][h * 2 + 1]);
        *reinterpret_cast<float2*>(cp + nf * 8) = v;
      }
    }
  }
}

// ---------------- merged GEMM launches ---------------------------------------
__global__ void __launch_bounds__(256, 2) stage1_kernel() {
  const int n0 = blockIdx.x * 64;
  const int y = blockIdx.y;
  if (y < 16) {
    gemm1_core(g_x_h, g_x_l, g_sg_h, g_sg_l, g_su_h, g_su_l,
               g_Hs_h, g_Hs_l, y * 128, T_TOK, n0, nullptr, 0);
  } else {
    const int ti = y - 16;
    if (ti >= g_ntiles) return;
    const int e = g_tile_e[ti];
    const size_t wo = (size_t)e * SW;
    gemm1_core(g_xs_h, g_xs_l, g_gw_h + wo, g_gw_l + wo, g_uw_h + wo, g_uw_l + wo,
               g_Hr_h, g_Hr_l, g_tile_m[ti], g_off[e + 1], n0, g_perm, 1);
  }
}

__global__ void __launch_bounds__(256, 2) stage2_kernel(float* __restrict__ out) {
  const int n0 = blockIdx.x * 64;
  const int y = blockIdx.y;
  if (y < 16) {
    gemm2_core(g_Hs_h, g_Hs_l, g_sd_h, g_sd_l, out, y * 128, T_TOK, n0);
  } else {
    const int ti = y - 16;
    if (ti >= g_ntiles) return;
    const int e = g_tile_e[ti];
    const size_t wo = (size_t)e * SW;
    gemm2_core(g_Hr_h, g_Hr_l, g_dw_h + wo, g_dw_l + wo, g_R,
               g_tile_m[ti], g_off[e + 1], n0);
  }
}

// ---------------- launch -----------------------------------------------------
extern "C" void kernel_launch(void* const* d_in, const int* in_sizes, int n_in,
                              void* d_out, int out_size) {
  const float* x  = (const float*)d_in[0];
  const float* rw = (const float*)d_in[1];
  const float* gw = (const float*)d_in[2];
  const float* uw = (const float*)d_in[3];
  const float* dw = (const float*)d_in[4];
  const float* sg = (const float*)d_in[5];
  const float* su = (const float*)d_in[6];
  const float* sd = (const float*)d_in[7];
  float* out = (float*)d_out;

  cudaFuncSetAttribute(stage1_kernel, cudaFuncAttributeMaxDynamicSharedMemorySize, S1_SMEM);
  cudaFuncSetAttribute(stage2_kernel, cudaFuncAttributeMaxDynamicSharedMemorySize, S2_SMEM);

  // #1 router, #2 plan, #3 split_all
  router_kernel<<<T_TOK / 8, 256>>>(x, rw);
  plan_kernel<<<1, 256>>>();
  const int splitN = 3 * EW4 + 3 * SW4;
  split_all_kernel<<<(splitN + 255) / 256, 256>>>(
      (const float4*)gw, (const float4*)uw, (const float4*)dw,
      (const float4*)sg, (const float4*)su, (const float4*)sd);

  // #4 stage1 (profiled slot), #5 stage2, #6 scatter-add
  dim3 g1(32, 40);
  dim3 g2(32, 40);
  stage1_kernel<<<g1, 256, S1_SMEM>>>();
  stage2_kernel<<<g2, 256, S2_SMEM>>>(out);
  scatter_add_kernel<<<(T_TOK * DIM / 4) / 256, 256>>>((float4*)out);
}

// round 11
// speedup vs baseline: 1.4581x; 1.4581x over previous
#include <cuda_runtime.h>
#include <math.h>
#include <stdint.h>

#define T_TOK 2048
#define DIM   2048
#define NEXP  8
#define EW    (NEXP * DIM * DIM)
#define SW    (DIM * DIM)
#define EW4   (EW / 4)
#define SW4   (SW / 4)

// ---------------- scratch (device globals) ----------------------------------
__device__ uint16_t g_gw_h[EW], g_gw_l[EW];
__device__ uint16_t g_uw_h[EW], g_uw_l[EW];
__device__ uint16_t g_dw_h[EW], g_dw_l[EW];
__device__ uint16_t g_sg_h[SW], g_sg_l[SW];
__device__ uint16_t g_su_h[SW], g_su_l[SW];
__device__ uint16_t g_sd_h[SW], g_sd_l[SW];
__device__ uint16_t g_x_h [SW], g_x_l [SW];
__device__ uint16_t g_xs_h[SW], g_xs_l[SW];
__device__ uint16_t g_Hs_h[SW], g_Hs_l[SW];
__device__ uint16_t g_Hr_h[SW], g_Hr_l[SW];
__device__ float    g_R[T_TOK * DIM];
__device__ int g_off[NEXP + 1];
__device__ int g_eidx[T_TOK], g_perm[T_TOK];
__device__ int g_tile_e[32], g_tile_m[32], g_ntiles;

// ---------------- helpers ----------------------------------------------------
__device__ __forceinline__ uint32_t smem_u32(const void* p) {
  uint32_t a;
  asm("{ .reg .u64 t; cvta.to.shared.u64 t, %1; cvt.u32.u64 %0, t; }" : "=r"(a) : "l"(p));
  return a;
}
__device__ __forceinline__ void cp16(uint32_t dst, const void* src) {
  asm volatile("cp.async.cg.shared.global [%0], [%1], 16;" :: "r"(dst), "l"(src));
}
__device__ __forceinline__ uint32_t pack_hi(float x, float y) {
  return __byte_perm(__float_as_uint(x), __float_as_uint(y), 0x7632);
}
__device__ __forceinline__ uint32_t pack_lo(float x, float y) {
  float lx = x - __uint_as_float(__float_as_uint(x) & 0xFFFF0000u);
  float ly = y - __uint_as_float(__float_as_uint(y) & 0xFFFF0000u);
  uint32_t r;
  asm("cvt.rn.bf16x2.f32 %0, %1, %2;" : "=r"(r) : "f"(ly), "f"(lx));
  return r;
}
__device__ __forceinline__ void mma16816(float* d, const uint32_t* a,
                                         uint32_t b0, uint32_t b1) {
  asm volatile("mma.sync.aligned.m16n8k16.row.col.f32.bf16.bf16.f32 "
               "{%0,%1,%2,%3}, {%4,%5,%6,%7}, {%8,%9}, {%0,%1,%2,%3};"
               : "+f"(d[0]), "+f"(d[1]), "+f"(d[2]), "+f"(d[3])
               : "r"(a[0]), "r"(a[1]), "r"(a[2]), "r"(a[3]), "r"(b0), "r"(b1));
}
#define LDSM4(r, a)                                                            \
  asm volatile("ldmatrix.sync.aligned.m8n8.x4.shared.b16 {%0,%1,%2,%3}, [%4];" \
    : "=r"((r)[0]), "=r"((r)[1]), "=r"((r)[2]), "=r"((r)[3]) : "r"(a))
#define LDSM4T(r, a)                                                           \
  asm volatile("ldmatrix.sync.aligned.m8n8.x4.trans.shared.b16 {%0,%1,%2,%3}, [%4];" \
    : "=r"((r)[0]), "=r"((r)[1]), "=r"((r)[2]), "=r"((r)[3]) : "r"(a))

// ---------------- setup kernels ----------------------------------------------
__global__ void router_kernel(const float* __restrict__ x,
                              const float* __restrict__ rw) {
  int tok  = (blockIdx.x * blockDim.x + threadIdx.x) >> 5;
  int lane = threadIdx.x & 31;
  if (tok >= T_TOK) return;
  const float* xr = x + (size_t)tok * DIM;
  float acc[NEXP];
#pragma unroll
  for (int e = 0; e < NEXP; e++) acc[e] = 0.f;
  for (int k = lane; k < DIM; k += 32) {
    float xv = xr[k];
    const float4* w4 = reinterpret_cast<const float4*>(rw + (size_t)k * NEXP);
    float4 w0 = w4[0], w1 = w4[1];
    acc[0] = fmaf(xv, w0.x, acc[0]); acc[1] = fmaf(xv, w0.y, acc[1]);
    acc[2] = fmaf(xv, w0.z, acc[2]); acc[3] = fmaf(xv, w0.w, acc[3]);
    acc[4] = fmaf(xv, w1.x, acc[4]); acc[5] = fmaf(xv, w1.y, acc[5]);
    acc[6] = fmaf(xv, w1.z, acc[6]); acc[7] = fmaf(xv, w1.w, acc[7]);
  }
#pragma unroll
  for (int o = 16; o > 0; o >>= 1)
#pragma unroll
    for (int e = 0; e < NEXP; e++)
      acc[e] += __shfl_down_sync(0xffffffffu, acc[e], o);
  float sc = 0.f;
  if (lane == 0) {
    float mx = acc[0]; int im = 0;
#pragma unroll
    for (int e = 1; e < NEXP; e++) if (acc[e] > mx) { mx = acc[e]; im = e; }
    sc = 1.f / (1.f + expf(-mx));
    g_eidx[tok] = im;
  }
  sc = __shfl_sync(0xffffffffu, sc, 0);
  const float4* x4 = reinterpret_cast<const float4*>(xr);
  uint2* xh = reinterpret_cast<uint2*>(g_x_h)  + (size_t)tok * (DIM / 4);
  uint2* xl = reinterpret_cast<uint2*>(g_x_l)  + (size_t)tok * (DIM / 4);
  uint2* sh = reinterpret_cast<uint2*>(g_xs_h) + (size_t)tok * (DIM / 4);
  uint2* sl = reinterpret_cast<uint2*>(g_xs_l) + (size_t)tok * (DIM / 4);
  for (int k = lane; k < DIM / 4; k += 32) {
    float4 v = x4[k];
    uint2 h, l;
    h.x = pack_hi(v.x, v.y); h.y = pack_hi(v.z, v.w);
    l.x = pack_lo(v.x, v.y); l.y = pack_lo(v.z, v.w);
    xh[k] = h; xl[k] = l;
    float4 s = make_float4(v.x * sc, v.y * sc, v.z * sc, v.w * sc);
    h.x = pack_hi(s.x, s.y); h.y = pack_hi(s.z, s.w);
    l.x = pack_lo(s.x, s.y); l.y = pack_lo(s.z, s.w);
    sh[k] = h; sl[k] = l;
  }
}

__global__ void plan_kernel() {
  __shared__ int cnt[NEXP], cur[NEXP];
  int t = threadIdx.x;
  if (t < NEXP) cnt[t] = 0;
  __syncthreads();
  for (int i = t; i < T_TOK; i += 256) atomicAdd(&cnt[g_eidx[i]], 1);
  __syncthreads();
  if (t == 0) {
    int o = 0, nt = 0;
    for (int e = 0; e < NEXP; e++) {
      g_off[e] = o; cur[e] = o;
      int c = cnt[e];
      for (int m = 0; m < c; m += 128) { g_tile_e[nt] = e; g_tile_m[nt] = o + m; nt++; }
      o += c;
    }
    g_off[NEXP] = o;
    g_ntiles = nt;
  }
  __syncthreads();
  for (int i = t; i < T_TOK; i += 256) {
    int e = g_eidx[i];
    int p = atomicAdd(&cur[e], 1);
    g_perm[p] = i;
  }
}

__global__ void split_all_kernel(const float4* __restrict__ gw, const float4* __restrict__ uw,
                                 const float4* __restrict__ dw, const float4* __restrict__ sg,
                                 const float4* __restrict__ su, const float4* __restrict__ sd) {
  int i = blockIdx.x * blockDim.x + threadIdx.x;
  const float4* src; uint2 *hi, *lo; int j;
  if      (i < EW4)            { src = gw; hi = (uint2*)g_gw_h; lo = (uint2*)g_gw_l; j = i; }
  else if (i < 2 * EW4)        { src = uw; hi = (uint2*)g_uw_h; lo = (uint2*)g_uw_l; j = i - EW4; }
  else if (i < 3 * EW4)        { src = dw; hi = (uint2*)g_dw_h; lo = (uint2*)g_dw_l; j = i - 2 * EW4; }
  else if (i < 3 * EW4 + SW4)  { src = sg; hi = (uint2*)g_sg_h; lo = (uint2*)g_sg_l; j = i - 3 * EW4; }
  else if (i < 3 * EW4 + 2 * SW4) { src = su; hi = (uint2*)g_su_h; lo = (uint2*)g_su_l; j = i - 3 * EW4 - SW4; }
  else if (i < 3 * EW4 + 3 * SW4) { src = sd; hi = (uint2*)g_sd_h; lo = (uint2*)g_sd_l; j = i - 3 * EW4 - 2 * SW4; }
  else return;
  float4 v = src[j];
  uint2 h, l;
  h.x = pack_hi(v.x, v.y); h.y = pack_hi(v.z, v.w);
  l.x = pack_lo(v.x, v.y); l.y = pack_lo(v.z, v.w);
  hi[j] = h; lo[j] = l;
}

__global__ void scatter_add_kernel(float4* __restrict__ out) {
  int i = blockIdx.x * blockDim.x + threadIdx.x;
  if (i >= T_TOK * DIM / 4) return;
  int p = i >> 9;
  int j = i & 511;
  int t = g_perm[p];
  const float4* R4 = reinterpret_cast<const float4*>(g_R);
  float4 r = R4[i];
  float4 o = out[(size_t)t * 512 + j];
  o.x += r.x; o.y += r.y; o.z += r.z; o.w += r.w;
  out[(size_t)t * 512 + j] = o;
}

// ---------------- stage1: fused gate/up GEMM, tile 128x64, 3-stage ----------
// (FROZEN: byte-identical to round-8 core, the best-measured configuration)
#define BK      32
#define NSTG    3
#define S1_LDB  144
#define S1_GH   18432
#define S1_GL   23040
#define S1_UH   27648
#define S1_UL   32256
#define S1_STG  36864
#define S1_SMEM (NSTG * S1_STG)
#define NCHUNK  (DIM / BK)

__device__ __forceinline__ void gemm1_core(
    const uint16_t* __restrict__ Ah, const uint16_t* __restrict__ Al,
    const uint16_t* __restrict__ Gh, const uint16_t* __restrict__ Gl,
    const uint16_t* __restrict__ Uh, const uint16_t* __restrict__ Ul,
    uint16_t* __restrict__ Hh, uint16_t* __restrict__ Hl,
    int m0, int mEnd, int n0, const int* __restrict__ perm, int gather) {
  extern __shared__ char smc[];
  const uint32_t smu = smem_u32(smc);
  const int t = threadIdx.x;
  const int lane = t & 31;
  const int wid  = t >> 5;
  const int wm = wid >> 1;
  const int wn = wid & 1;
  const int rsel = lane & 15;
  const int csel = lane >> 4;

  const int am = t >> 1, ahalf = t & 1;
  const int ga = m0 + am;
  const bool av = ga < mEnd;
  const int arow = gather ? (av ? perm[ga] : 0) : (av ? ga : 0);
  const uint16_t* aSrcH = Ah + (size_t)arow * DIM + ahalf * 16;
  const uint16_t* aSrcL = Al + (size_t)arow * DIM + ahalf * 16;
  const uint32_t dA = smu + (uint32_t)(am * 144 + ahalf * 32);
  const int brow = t >> 3, bseg = t & 7;
  const size_t bOff = (size_t)brow * DIM + n0 + bseg * 8;
  const uint32_t dB = smu + (uint32_t)(brow * S1_LDB + bseg * 16);

  float accG[2][4][4], accU[2][4][4];
#pragma unroll
  for (int i = 0; i < 2; i++)
#pragma unroll
    for (int j = 0; j < 4; j++)
#pragma unroll
      for (int q = 0; q < 4; q++) { accG[i][j][q] = 0.f; accU[i][j][q] = 0.f; }

  auto fill = [&](int st, int c) {
    const int k0 = c * BK;
    const uint32_t sb = (uint32_t)st * S1_STG;
    cp16(dA + sb,      aSrcH + k0);
    cp16(dA + sb + 16, aSrcH + k0 + 8);
    cp16(dA + sb + 64, aSrcL + k0);
    cp16(dA + sb + 80, aSrcL + k0 + 8);
    const size_t bk = bOff + (size_t)k0 * DIM;
    cp16(dB + sb + S1_GH, Gh + bk);
    cp16(dB + sb + S1_GL, Gl + bk);
    cp16(dB + sb + S1_UH, Uh + bk);
    cp16(dB + sb + S1_UL, Ul + bk);
  };

#pragma unroll
  for (int s = 0; s < NSTG - 1; s++) {
    fill(s, s);
    asm volatile("cp.async.commit_group;" ::: "memory");
  }

  for (int c = 0; c < NCHUNK; c++) {
    asm volatile("cp.async.wait_group %0;" :: "n"(NSTG - 2) : "memory");
    __syncthreads();
    if (c + NSTG - 1 < NCHUNK) fill((c + NSTG - 1) % NSTG, c + NSTG - 1);
    asm volatile("cp.async.commit_group;" ::: "memory");

    const uint32_t stg = smu + (uint32_t)((c % NSTG) * S1_STG);
#pragma unroll
    for (int ks = 0; ks < 2; ks++) {
      uint32_t ah[2][4], al[2][4];
#pragma unroll
      for (int mt = 0; mt < 2; mt++) {
        uint32_t ra = stg + (uint32_t)((wm * 32 + mt * 16 + rsel) * 144 +
                                       ks * 32 + csel * 16);
        LDSM4(ah[mt], ra);
        LDSM4(al[mt], ra + 64);
      }
#pragma unroll
      for (int np = 0; np < 2; np++) {
        uint32_t rb = stg + (uint32_t)((ks * 16 + rsel) * S1_LDB +
                                       (wn * 32 + np * 16 + csel * 8) * 2);
        uint32_t gh[4], gl[4], uh[4], ul[4];
        LDSM4T(gh, rb + S1_GH);
        LDSM4T(gl, rb + S1_GL);
        LDSM4T(uh, rb + S1_UH);
        LDSM4T(ul, rb + S1_UL);
        const int f0 = np * 2, f1 = np * 2 + 1;
        // term hh (8 independent accumulators)
        mma16816(accG[0][f0], ah[0], gh[0], gh[1]);
        mma16816(accG[1][f0], ah[1], gh[0], gh[1]);
        mma16816(accG[0][f1], ah[0], gh[2], gh[3]);
        mma16816(accG[1][f1], ah[1], gh[2], gh[3]);
        mma16816(accU[0][f0], ah[0], uh[0], uh[1]);
        mma16816(accU[1][f0], ah[1], uh[0], uh[1]);
        mma16816(accU[0][f1], ah[0], uh[2], uh[3]);
        mma16816(accU[1][f1], ah[1], uh[2], uh[3]);
        // term hl
        mma16816(accG[0][f0], ah[0], gl[0], gl[1]);
        mma16816(accG[1][f0], ah[1], gl[0], gl[1]);
        mma16816(accG[0][f1], ah[0], gl[2], gl[3]);
        mma16816(accG[1][f1], ah[1], gl[2], gl[3]);
        mma16816(accU[0][f0], ah[0], ul[0], ul[1]);
        mma16816(accU[1][f0], ah[1], ul[0], ul[1]);
        mma16816(accU[0][f1], ah[0], ul[2], ul[3]);
        mma16816(accU[1][f1], ah[1], ul[2], ul[3]);
        // term lh
        mma16816(accG[0][f0], al[0], gh[0], gh[1]);
        mma16816(accG[1][f0], al[1], gh[0], gh[1]);
        mma16816(accG[0][f1], al[0], gh[2], gh[3]);
        mma16816(accG[1][f1], al[1], gh[2], gh[3]);
        mma16816(accU[0][f0], al[0], uh[0], uh[1]);
        mma16816(accU[1][f0], al[1], uh[0], uh[1]);
        mma16816(accU[0][f1], al[0], uh[2], uh[3]);
        mma16816(accU[1][f1], al[1], uh[2], uh[3]);
      }
    }
  }

#pragma unroll
  for (int mt = 0; mt < 2; mt++) {
#pragma unroll
    for (int h = 0; h < 2; h++) {
      const int row = m0 + wm * 32 + mt * 16 + (lane >> 2) + h * 8;
      if (row >= mEnd) continue;
      const int colb = n0 + wn * 32 + (lane & 3) * 2;
      uint16_t* hpH = Hh + (size_t)row * DIM + colb;
      uint16_t* hpL = Hl + (size_t)row * DIM + colb;
#pragma unroll
      for (int nf = 0; nf < 4; nf++) {
        float g0 = accG[mt][nf][h * 2],     u0 = accU[mt][nf][h * 2];
        float g1 = accG[mt][nf][h * 2 + 1], u1 = accU[mt][nf][h * 2 + 1];
        float h0 = g0 / (1.f + expf(-g0)) * u0;
        float h1 = g1 / (1.f + expf(-g1)) * u1;
        *reinterpret_cast<uint32_t*>(hpH + nf * 8) = pack_hi(h0, h1);
        *reinterpret_cast<uint32_t*>(hpL + nf * 8) = pack_lo(h0, h1);
      }
    }
  }
}

// ---------------- stage2: down GEMM, tile 128x64, 3-stage --------------------
// r8-style ordering: ALL fragment loads batched up front, then 24 MMAs.
#define S2_LDB  144
#define S2_BH   18432
#define S2_BL   23040
#define S2_STG  27648
#define S2_SMEM (NSTG * S2_STG)

__device__ __forceinline__ void gemm2_core(
    const uint16_t* __restrict__ Ah, const uint16_t* __restrict__ Al,
    const uint16_t* __restrict__ Bh, const uint16_t* __restrict__ Bl,
    float* __restrict__ C, int m0, int mEnd, int n0) {
  extern __shared__ char smc[];
  const uint32_t smu = smem_u32(smc);
  const int t = threadIdx.x;
  const int lane = t & 31;
  const int wid  = t >> 5;
  const int wm = wid >> 1;
  const int wn = wid & 1;
  const int rsel = lane & 15;
  const int csel = lane >> 4;

  const int am = t >> 1, ahalf = t & 1;
  const int ga = m0 + am;
  const bool av = ga < mEnd;
  const int arow = av ? ga : 0;
  const uint16_t* aSrcH = Ah + (size_t)arow * DIM + ahalf * 16;
  const uint16_t* aSrcL = Al + (size_t)arow * DIM + ahalf * 16;
  const uint32_t dA = smu + (uint32_t)(am * 144 + ahalf * 32);
  const int brow = t >> 3, bseg = t & 7;
  const size_t bOff = (size_t)brow * DIM + n0 + bseg * 8;
  const uint32_t dB = smu + (uint32_t)(brow * S2_LDB + bseg * 16);

  float acc[2][4][4];
#pragma unroll
  for (int i = 0; i < 2; i++)
#pragma unroll
    for (int j = 0; j < 4; j++)
#pragma unroll
      for (int q = 0; q < 4; q++) acc[i][j][q] = 0.f;

  auto fill = [&](int st, int c) {
    const int k0 = c * BK;
    const uint32_t sb = (uint32_t)st * S2_STG;
    cp16(dA + sb,      aSrcH + k0);
    cp16(dA + sb + 16, aSrcH + k0 + 8);
    cp16(dA + sb + 64, aSrcL + k0);
    cp16(dA + sb + 80, aSrcL + k0 + 8);
    const size_t bk = bOff + (size_t)k0 * DIM;
    cp16(dB + sb + S2_BH, Bh + bk);
    cp16(dB + sb + S2_BL, Bl + bk);
  };

#pragma unroll
  for (int s = 0; s < NSTG - 1; s++) {
    fill(s, s);
    asm volatile("cp.async.commit_group;" ::: "memory");
  }

  for (int c = 0; c < NCHUNK; c++) {
    asm volatile("cp.async.wait_group %0;" :: "n"(NSTG - 2) : "memory");
    __syncthreads();
    if (c + NSTG - 1 < NCHUNK) fill((c + NSTG - 1) % NSTG, c + NSTG - 1);
    asm volatile("cp.async.commit_group;" ::: "memory");

    const uint32_t stg = smu + (uint32_t)((c % NSTG) * S2_STG);
#pragma unroll
    for (int ks = 0; ks < 2; ks++) {
      // ALL fragment loads batched up front (r8 pattern)
      uint32_t ah[2][4], al[2][4];
#pragma unroll
      for (int mt = 0; mt < 2; mt++) {
        uint32_t ra = stg + (uint32_t)((wm * 32 + mt * 16 + rsel) * 144 +
                                       ks * 32 + csel * 16);
        LDSM4(ah[mt], ra);
        LDSM4(al[mt], ra + 64);
      }
      uint32_t rb = stg + (uint32_t)((ks * 16 + rsel) * S2_LDB +
                                     (wn * 32 + csel * 8) * 2);
      uint32_t bh0[4], bh1[4], bl0[4], bl1[4];
      LDSM4T(bh0, rb + S2_BH);
      LDSM4T(bh1, rb + S2_BH + 32);
      LDSM4T(bl0, rb + S2_BL);
      LDSM4T(bl1, rb + S2_BL + 32);
      // term hh (8 independent accumulators)
      mma16816(acc[0][0], ah[0], bh0[0], bh0[1]);
      mma16816(acc[1][0], ah[1], bh0[0], bh0[1]);
      mma16816(acc[0][1], ah[0], bh0[2], bh0[3]);
      mma16816(acc[1][1], ah[1], bh0[2], bh0[3]);
      mma16816(acc[0][2], ah[0], bh1[0], bh1[1]);
      mma16816(acc[1][2], ah[1], bh1[0], bh1[1]);
      mma16816(acc[0][3], ah[0], bh1[2], bh1[3]);
      mma16816(acc[1][3], ah[1], bh1[2], bh1[3]);
      // term hl
      mma16816(acc[0][0], ah[0], bl0[0], bl0[1]);
      mma16816(acc[1][0], ah[1], bl0[0], bl0[1]);
      mma16816(acc[0][1], ah[0], bl0[2], bl0[3]);
      mma16816(acc[1][1], ah[1], bl0[2], bl0[3]);
      mma16816(acc[0][2], ah[0], bl1[0], bl1[1]);
      mma16816(acc[1][2], ah[1], bl1[0], bl1[1]);
      mma16816(acc[0][3], ah[0], bl1[2], bl1[3]);
      mma16816(acc[1][3], ah[1], bl1[2], bl1[3]);
      // term lh
      mma16816(acc[0][0], al[0], bh0[0], bh0[1]);
      mma16816(acc[1][0], al[1], bh0[0], bh0[1]);
      mma16816(acc[0][1], al[0], bh0[2], bh0[3]);
      mma16816(acc[1][1], al[1], bh0[2], bh0[3]);
      mma16816(acc[0][2], al[0], bh1[0], bh1[1]);
      mma16816(acc[1][2], al[1], bh1[0], bh1[1]);
      mma16816(acc[0][3], al[0], bh1[2], bh1[3]);
      mma16816(acc[1][3], al[1], bh1[2], bh1[3]);
    }
  }

#pragma unroll
  for (int mt = 0; mt < 2; mt++) {
#pragma unroll
    for (int h = 0; h < 2; h++) {
      const int row = m0 + wm * 32 + mt * 16 + (lane >> 2) + h * 8;
      if (row >= mEnd) continue;
      float* cp = C + (size_t)row * DIM + n0 + wn * 32 + (lane & 3) * 2;
#pragma unroll
      for (int nf = 0; nf < 4; nf++) {
        float2 v = make_float2(acc[mt][nf][h * 2], acc[mt][nf][h * 2 + 1]);
        *reinterpret_cast<float2*>(cp + nf * 8) = v;
      }
    }
  }
}

// ---------------- merged GEMM launches ---------------------------------------
__global__ void __launch_bounds__(256, 2) stage1_kernel() {
  const int n0 = blockIdx.x * 64;
  const int y = blockIdx.y;
  if (y < 16) {
    gemm1_core(g_x_h, g_x_l, g_sg_h, g_sg_l, g_su_h, g_su_l,
               g_Hs_h, g_Hs_l, y * 128, T_TOK, n0, nullptr, 0);
  } else {
    const int ti = y - 16;
    if (ti >= g_ntiles) return;
    const int e = g_tile_e[ti];
    const size_t wo = (size_t)e * SW;
    gemm1_core(g_xs_h, g_xs_l, g_gw_h + wo, g_gw_l + wo, g_uw_h + wo, g_uw_l + wo,
               g_Hr_h, g_Hr_l, g_tile_m[ti], g_off[e + 1], n0, g_perm, 1);
  }
}

__global__ void __launch_bounds__(256, 2) stage2_kernel(float* __restrict__ out) {
  const int n0 = blockIdx.x * 64;
  const int y = blockIdx.y;
  if (y < 16) {
    gemm2_core(g_Hs_h, g_Hs_l, g_sd_h, g_sd_l, out, y * 128, T_TOK, n0);
  } else {
    const int ti = y - 16;
    if (ti >= g_ntiles) return;
    const int e = g_tile_e[ti];
    const size_t wo = (size_t)e * SW;
    gemm2_core(g_Hr_h, g_Hr_l, g_dw_h + wo, g_dw_l + wo, g_R,
               g_tile_m[ti], g_off[e + 1], n0);
  }
}

// ---------------- launch -----------------------------------------------------
extern "C" void kernel_launch(void* const* d_in, const int* in_sizes, int n_in,
                              void* d_out, int out_size) {
  const float* x  = (const float*)d_in[0];
  const float* rw = (const float*)d_in[1];
  const float* gw = (const float*)d_in[2];
  const float* uw = (const float*)d_in[3];
  const float* dw = (const float*)d_in[4];
  const float* sg = (const float*)d_in[5];
  const float* su = (const float*)d_in[6];
  const float* sd = (const float*)d_in[7];
  float* out = (float*)d_out;

  cudaFuncSetAttribute(stage1_kernel, cudaFuncAttributeMaxDynamicSharedMemorySize, S1_SMEM);
  cudaFuncSetAttribute(stage2_kernel, cudaFuncAttributeMaxDynamicSharedMemorySize, S2_SMEM);

  // #1 router, #2 plan, #3 split_all
  router_kernel<<<T_TOK / 8, 256>>>(x, rw);
  plan_kernel<<<1, 256>>>();
  const int splitN = 3 * EW4 + 3 * SW4;
  split_all_kernel<<<(splitN + 255) / 256, 256>>>(
      (const float4*)gw, (const float4*)uw, (const float4*)dw,
      (const float4*)sg, (const float4*)su, (const float4*)sd);

  // #4 stage1 (profiled slot), #5 stage2, #6 scatter-add
  dim3 g1(32, 40);
  dim3 g2(32, 40);
  stage1_kernel<<<g1, 256, S1_SMEM>>>();
  stage2_kernel<<<g2, 256, S2_SMEM>>>(out);
  scatter_add_kernel<<<(T_TOK * DIM / 4) / 256, 256>>>((float4*)out);
}

// round 13
// speedup vs baseline: 1.5060x; 1.0328x over previous
#include <cuda_runtime.h>
#include <math.h>
#include <stdint.h>

#define T_TOK 2048
#define DIM   2048
#define NEXP  8
#define EW    (NEXP * DIM * DIM)
#define SW    (DIM * DIM)
#define EW4   (EW / 4)
#define SW4   (SW / 4)

// ---------------- scratch (device globals) ----------------------------------
__device__ uint16_t g_gw_h[EW], g_gw_l[EW];
__device__ uint16_t g_uw_h[EW], g_uw_l[EW];
__device__ uint16_t g_dw_h[EW], g_dw_l[EW];
__device__ uint16_t g_sg_h[SW], g_sg_l[SW];
__device__ uint16_t g_su_h[SW], g_su_l[SW];
__device__ uint16_t g_sd_h[SW], g_sd_l[SW];
__device__ uint16_t g_x_h [SW], g_x_l [SW];
__device__ uint16_t g_xs_h[SW], g_xs_l[SW];
__device__ uint16_t g_Hs_h[SW], g_Hs_l[SW];
__device__ uint16_t g_Hr_h[SW], g_Hr_l[SW];
__device__ float    g_R[T_TOK * DIM];
__device__ int g_off[NEXP + 1];
__device__ int g_eidx[T_TOK], g_perm[T_TOK];
__device__ int g_tile_e[32], g_tile_m[32], g_ntiles;

// ---------------- helpers ----------------------------------------------------
__device__ __forceinline__ uint32_t smem_u32(const void* p) {
  uint32_t a;
  asm("{ .reg .u64 t; cvta.to.shared.u64 t, %1; cvt.u32.u64 %0, t; }" : "=r"(a) : "l"(p));
  return a;
}
__device__ __forceinline__ void cp16(uint32_t dst, const void* src) {
  asm volatile("cp.async.cg.shared.global [%0], [%1], 16;" :: "r"(dst), "l"(src));
}
__device__ __forceinline__ uint32_t pack_hi(float x, float y) {
  return __byte_perm(__float_as_uint(x), __float_as_uint(y), 0x7632);
}
__device__ __forceinline__ uint32_t pack_lo(float x, float y) {
  float lx = x - __uint_as_float(__float_as_uint(x) & 0xFFFF0000u);
  float ly = y - __uint_as_float(__float_as_uint(y) & 0xFFFF0000u);
  uint32_t r;
  asm("cvt.rn.bf16x2.f32 %0, %1, %2;" : "=r"(r) : "f"(ly), "f"(lx));
  return r;
}
__device__ __forceinline__ void mma16816(float* d, const uint32_t* a,
                                         uint32_t b0, uint32_t b1) {
  asm volatile("mma.sync.aligned.m16n8k16.row.col.f32.bf16.bf16.f32 "
               "{%0,%1,%2,%3}, {%4,%5,%6,%7}, {%8,%9}, {%0,%1,%2,%3};"
               : "+f"(d[0]), "+f"(d[1]), "+f"(d[2]), "+f"(d[3])
               : "r"(a[0]), "r"(a[1]), "r"(a[2]), "r"(a[3]), "r"(b0), "r"(b1));
}
#define LDSM4(r, a)                                                            \
  asm volatile("ldmatrix.sync.aligned.m8n8.x4.shared.b16 {%0,%1,%2,%3}, [%4];" \
    : "=r"((r)[0]), "=r"((r)[1]), "=r"((r)[2]), "=r"((r)[3]) : "r"(a))
#define LDSM4T(r, a)                                                           \
  asm volatile("ldmatrix.sync.aligned.m8n8.x4.trans.shared.b16 {%0,%1,%2,%3}, [%4];" \
    : "=r"((r)[0]), "=r"((r)[1]), "=r"((r)[2]), "=r"((r)[3]) : "r"(a))

// ---------------- setup kernels ----------------------------------------------
__global__ void router_kernel(const float* __restrict__ x,
                              const float* __restrict__ rw) {
  int tok  = (blockIdx.x * blockDim.x + threadIdx.x) >> 5;
  int lane = threadIdx.x & 31;
  if (tok >= T_TOK) return;
  const float* xr = x + (size_t)tok * DIM;
  float acc[NEXP];
#pragma unroll
  for (int e = 0; e < NEXP; e++) acc[e] = 0.f;
  for (int k = lane; k < DIM; k += 32) {
    float xv = xr[k];
    const float4* w4 = reinterpret_cast<const float4*>(rw + (size_t)k * NEXP);
    float4 w0 = w4[0], w1 = w4[1];
    acc[0] = fmaf(xv, w0.x, acc[0]); acc[1] = fmaf(xv, w0.y, acc[1]);
    acc[2] = fmaf(xv, w0.z, acc[2]); acc[3] = fmaf(xv, w0.w, acc[3]);
    acc[4] = fmaf(xv, w1.x, acc[4]); acc[5] = fmaf(xv, w1.y, acc[5]);
    acc[6] = fmaf(xv, w1.z, acc[6]); acc[7] = fmaf(xv, w1.w, acc[7]);
  }
#pragma unroll
  for (int o = 16; o > 0; o >>= 1)
#pragma unroll
    for (int e = 0; e < NEXP; e++)
      acc[e] += __shfl_down_sync(0xffffffffu, acc[e], o);
  float sc = 0.f;
  if (lane == 0) {
    float mx = acc[0]; int im = 0;
#pragma unroll
    for (int e = 1; e < NEXP; e++) if (acc[e] > mx) { mx = acc[e]; im = e; }
    sc = 1.f / (1.f + expf(-mx));
    g_eidx[tok] = im;
  }
  sc = __shfl_sync(0xffffffffu, sc, 0);
  const float4* x4 = reinterpret_cast<const float4*>(xr);
  uint2* xh = reinterpret_cast<uint2*>(g_x_h)  + (size_t)tok * (DIM / 4);
  uint2* xl = reinterpret_cast<uint2*>(g_x_l)  + (size_t)tok * (DIM / 4);
  uint2* sh = reinterpret_cast<uint2*>(g_xs_h) + (size_t)tok * (DIM / 4);
  uint2* sl = reinterpret_cast<uint2*>(g_xs_l) + (size_t)tok * (DIM / 4);
  for (int k = lane; k < DIM / 4; k += 32) {
    float4 v = x4[k];
    uint2 h, l;
    h.x = pack_hi(v.x, v.y); h.y = pack_hi(v.z, v.w);
    l.x = pack_lo(v.x, v.y); l.y = pack_lo(v.z, v.w);
    xh[k] = h; xl[k] = l;
    float4 s = make_float4(v.x * sc, v.y * sc, v.z * sc, v.w * sc);
    h.x = pack_hi(s.x, s.y); h.y = pack_hi(s.z, s.w);
    l.x = pack_lo(s.x, s.y); l.y = pack_lo(s.z, s.w);
    sh[k] = h; sl[k] = l;
  }
}

__global__ void plan_kernel() {
  __shared__ int cnt[NEXP], cur[NEXP];
  int t = threadIdx.x;
  if (t < NEXP) cnt[t] = 0;
  __syncthreads();
  for (int i = t; i < T_TOK; i += 256) atomicAdd(&cnt[g_eidx[i]], 1);
  __syncthreads();
  if (t == 0) {
    int o = 0, nt = 0;
    for (int e = 0; e < NEXP; e++) {
      g_off[e] = o; cur[e] = o;
      int c = cnt[e];
      for (int m = 0; m < c; m += 128) { g_tile_e[nt] = e; g_tile_m[nt] = o + m; nt++; }
      o += c;
    }
    g_off[NEXP] = o;
    g_ntiles = nt;
  }
  __syncthreads();
  for (int i = t; i < T_TOK; i += 256) {
    int e = g_eidx[i];
    int p = atomicAdd(&cur[e], 1);
    g_perm[p] = i;
  }
}

__global__ void split_all_kernel(const float4* __restrict__ gw, const float4* __restrict__ uw,
                                 const float4* __restrict__ dw, const float4* __restrict__ sg,
                                 const float4* __restrict__ su, const float4* __restrict__ sd) {
  int i = blockIdx.x * blockDim.x + threadIdx.x;
  const float4* src; uint2 *hi, *lo; int j;
  if      (i < EW4)            { src = gw; hi = (uint2*)g_gw_h; lo = (uint2*)g_gw_l; j = i; }
  else if (i < 2 * EW4)        { src = uw; hi = (uint2*)g_uw_h; lo = (uint2*)g_uw_l; j = i - EW4; }
  else if (i < 3 * EW4)        { src = dw; hi = (uint2*)g_dw_h; lo = (uint2*)g_dw_l; j = i - 2 * EW4; }
  else if (i < 3 * EW4 + SW4)  { src = sg; hi = (uint2*)g_sg_h; lo = (uint2*)g_sg_l; j = i - 3 * EW4; }
  else if (i < 3 * EW4 + 2 * SW4) { src = su; hi = (uint2*)g_su_h; lo = (uint2*)g_su_l; j = i - 3 * EW4 - SW4; }
  else if (i < 3 * EW4 + 3 * SW4) { src = sd; hi = (uint2*)g_sd_h; lo = (uint2*)g_sd_l; j = i - 3 * EW4 - 2 * SW4; }
  else return;
  float4 v = src[j];
  uint2 h, l;
  h.x = pack_hi(v.x, v.y); h.y = pack_hi(v.z, v.w);
  l.x = pack_lo(v.x, v.y); l.y = pack_lo(v.z, v.w);
  hi[j] = h; lo[j] = l;
}

__global__ void scatter_add_kernel(float4* __restrict__ out) {
  int i = blockIdx.x * blockDim.x + threadIdx.x;
  if (i >= T_TOK * DIM / 4) return;
  int p = i >> 9;
  int j = i & 511;
  int t = g_perm[p];
  const float4* R4 = reinterpret_cast<const float4*>(g_R);
  float4 r = R4[i];
  float4 o = out[(size_t)t * 512 + j];
  o.x += r.x; o.y += r.y; o.z += r.z; o.w += r.w;
  out[(size_t)t * 512 + j] = o;
}

// ---------------- stage1: fused gate/up GEMM, tile 128x64, 3-stage ----------
// FROZEN r8 core + r8 boundary (wait -> sync -> fill -> commit).
#define BK      32
#define NSTG    3
#define S1_LDB  144
#define S1_GH   18432
#define S1_GL   23040
#define S1_UH   27648
#define S1_UL   32256
#define S1_STG  36864
#define S1_SMEM (NSTG * S1_STG)
#define NCHUNK  (DIM / BK)

__device__ __forceinline__ void gemm1_core(
    const uint16_t* __restrict__ Ah, const uint16_t* __restrict__ Al,
    const uint16_t* __restrict__ Gh, const uint16_t* __restrict__ Gl,
    const uint16_t* __restrict__ Uh, const uint16_t* __restrict__ Ul,
    uint16_t* __restrict__ Hh, uint16_t* __restrict__ Hl,
    int m0, int mEnd, int n0, const int* __restrict__ perm, int gather) {
  extern __shared__ char smc[];
  const uint32_t smu = smem_u32(smc);
  const int t = threadIdx.x;
  const int lane = t & 31;
  const int wid  = t >> 5;
  const int wm = wid >> 1;
  const int wn = wid & 1;
  const int rsel = lane & 15;
  const int csel = lane >> 4;

  const int am = t >> 1, ahalf = t & 1;
  const int ga = m0 + am;
  const bool av = ga < mEnd;
  const int arow = gather ? (av ? perm[ga] : 0) : (av ? ga : 0);
  const uint16_t* aSrcH = Ah + (size_t)arow * DIM + ahalf * 16;
  const uint16_t* aSrcL = Al + (size_t)arow * DIM + ahalf * 16;
  const uint32_t dA = smu + (uint32_t)(am * 144 + ahalf * 32);
  const int brow = t >> 3, bseg = t & 7;
  const size_t bOff = (size_t)brow * DIM + n0 + bseg * 8;
  const uint32_t dB = smu + (uint32_t)(brow * S1_LDB + bseg * 16);

  float accG[2][4][4], accU[2][4][4];
#pragma unroll
  for (int i = 0; i < 2; i++)
#pragma unroll
    for (int j = 0; j < 4; j++)
#pragma unroll
      for (int q = 0; q < 4; q++) { accG[i][j][q] = 0.f; accU[i][j][q] = 0.f; }

  auto fill = [&](int st, int c) {
    const int k0 = c * BK;
    const uint32_t sb = (uint32_t)st * S1_STG;
    cp16(dA + sb,      aSrcH + k0);
    cp16(dA + sb + 16, aSrcH + k0 + 8);
    cp16(dA + sb + 64, aSrcL + k0);
    cp16(dA + sb + 80, aSrcL + k0 + 8);
    const size_t bk = bOff + (size_t)k0 * DIM;
    cp16(dB + sb + S1_GH, Gh + bk);
    cp16(dB + sb + S1_GL, Gl + bk);
    cp16(dB + sb + S1_UH, Uh + bk);
    cp16(dB + sb + S1_UL, Ul + bk);
  };

#pragma unroll
  for (int s = 0; s < NSTG - 1; s++) {
    fill(s, s);
    asm volatile("cp.async.commit_group;" ::: "memory");
  }

  for (int c = 0; c < NCHUNK; c++) {
    asm volatile("cp.async.wait_group %0;" :: "n"(NSTG - 2) : "memory");
    __syncthreads();
    if (c + NSTG - 1 < NCHUNK) fill((c + NSTG - 1) % NSTG, c + NSTG - 1);
    asm volatile("cp.async.commit_group;" ::: "memory");

    const uint32_t stg = smu + (uint32_t)((c % NSTG) * S1_STG);
#pragma unroll
    for (int ks = 0; ks < 2; ks++) {
      uint32_t ah[2][4], al[2][4];
#pragma unroll
      for (int mt = 0; mt < 2; mt++) {
        uint32_t ra = stg + (uint32_t)((wm * 32 + mt * 16 + rsel) * 144 +
                                       ks * 32 + csel * 16);
        LDSM4(ah[mt], ra);
        LDSM4(al[mt], ra + 64);
      }
#pragma unroll
      for (int np = 0; np < 2; np++) {
        uint32_t rb = stg + (uint32_t)((ks * 16 + rsel) * S1_LDB +
                                       (wn * 32 + np * 16 + csel * 8) * 2);
        uint32_t gh[4], gl[4], uh[4], ul[4];
        LDSM4T(gh, rb + S1_GH);
        LDSM4T(gl, rb + S1_GL);
        LDSM4T(uh, rb + S1_UH);
        LDSM4T(ul, rb + S1_UL);
        const int f0 = np * 2, f1 = np * 2 + 1;
        // term hh (8 independent accumulators)
        mma16816(accG[0][f0], ah[0], gh[0], gh[1]);
        mma16816(accG[1][f0], ah[1], gh[0], gh[1]);
        mma16816(accG[0][f1], ah[0], gh[2], gh[3]);
        mma16816(accG[1][f1], ah[1], gh[2], gh[3]);
        mma16816(accU[0][f0], ah[0], uh[0], uh[1]);
        mma16816(accU[1][f0], ah[1], uh[0], uh[1]);
        mma16816(accU[0][f1], ah[0], uh[2], uh[3]);
        mma16816(accU[1][f1], ah[1], uh[2], uh[3]);
        // term hl
        mma16816(accG[0][f0], ah[0], gl[0], gl[1]);
        mma16816(accG[1][f0], ah[1], gl[0], gl[1]);
        mma16816(accG[0][f1], ah[0], gl[2], gl[3]);
        mma16816(accG[1][f1], ah[1], gl[2], gl[3]);
        mma16816(accU[0][f0], ah[0], ul[0], ul[1]);
        mma16816(accU[1][f0], ah[1], ul[0], ul[1]);
        mma16816(accU[0][f1], ah[0], ul[2], ul[3]);
        mma16816(accU[1][f1], ah[1], ul[2], ul[3]);
        // term lh
        mma16816(accG[0][f0], al[0], gh[0], gh[1]);
        mma16816(accG[1][f0], al[1], gh[0], gh[1]);
        mma16816(accG[0][f1], al[0], gh[2], gh[3]);
        mma16816(accG[1][f1], al[1], gh[2], gh[3]);
        mma16816(accU[0][f0], al[0], uh[0], uh[1]);
        mma16816(accU[1][f0], al[1], uh[0], uh[1]);
        mma16816(accU[0][f1], al[0], uh[2], uh[3]);
        mma16816(accU[1][f1], al[1], uh[2], uh[3]);
      }
    }
  }

#pragma unroll
  for (int mt = 0; mt < 2; mt++) {
#pragma unroll
    for (int h = 0; h < 2; h++) {
      const int row = m0 + wm * 32 + mt * 16 + (lane >> 2) + h * 8;
      if (row >= mEnd) continue;
      const int colb = n0 + wn * 32 + (lane & 3) * 2;
      uint16_t* hpH = Hh + (size_t)row * DIM + colb;
      uint16_t* hpL = Hl + (size_t)row * DIM + colb;
#pragma unroll
      for (int nf = 0; nf < 4; nf++) {
        float g0 = accG[mt][nf][h * 2],     u0 = accU[mt][nf][h * 2];
        float g1 = accG[mt][nf][h * 2 + 1], u1 = accU[mt][nf][h * 2 + 1];
        float h0 = g0 / (1.f + expf(-g0)) * u0;
        float h1 = g1 / (1.f + expf(-g1)) * u1;
        *reinterpret_cast<uint32_t*>(hpH + nf * 8) = pack_hi(h0, h1);
        *reinterpret_cast<uint32_t*>(hpL + nf * 8) = pack_lo(h0, h1);
      }
    }
  }
}

// ---------------- stage2: down GEMM, tile 128x128, 3-stage -------------------
// r8 config; boundary changed to CORRECT early-prefetch:
// sync -> fill(c+2) -> commit -> wait(NSTG-1) -> sync -> consume.
#define S2_LDB  272
#define S2_BH   18432
#define S2_BL   27136
#define S2_STG  35840
#define S2_SMEM (NSTG * S2_STG)

__device__ __forceinline__ void gemm2_core(
    const uint16_t* __restrict__ Ah, const uint16_t* __restrict__ Al,
    const uint16_t* __restrict__ Bh, const uint16_t* __restrict__ Bl,
    float* __restrict__ C, int m0, int mEnd, int n0) {
  extern __shared__ char smc[];
  const uint32_t smu = smem_u32(smc);
  const int t = threadIdx.x;
  const int lane = t & 31;
  const int wid  = t >> 5;
  const int wm = wid >> 1;
  const int wn = wid & 1;
  const int rsel = lane & 15;
  const int csel = lane >> 4;

  const int am = t >> 1, ahalf = t & 1;
  const int ga = m0 + am;
  const bool av = ga < mEnd;
  const int arow = av ? ga : 0;
  const uint16_t* aSrcH = Ah + (size_t)arow * DIM + ahalf * 16;
  const uint16_t* aSrcL = Al + (size_t)arow * DIM + ahalf * 16;
  const uint32_t dA = smu + (uint32_t)(am * 144 + ahalf * 32);
  const int brow = t >> 3, bseg = t & 7;
  const size_t bOff = (size_t)brow * DIM + n0 + bseg * 16;
  const uint32_t dB = smu + (uint32_t)(brow * S2_LDB + bseg * 32);

  float acc[2][8][4];
#pragma unroll
  for (int i = 0; i < 2; i++)
#pragma unroll
    for (int j = 0; j < 8; j++)
#pragma unroll
      for (int q = 0; q < 4; q++) acc[i][j][q] = 0.f;

  auto fill = [&](int st, int c) {
    const int k0 = c * BK;
    const uint32_t sb = (uint32_t)st * S2_STG;
    cp16(dA + sb,      aSrcH + k0);
    cp16(dA + sb + 16, aSrcH + k0 + 8);
    cp16(dA + sb + 64, aSrcL + k0);
    cp16(dA + sb + 80, aSrcL + k0 + 8);
    const size_t bk = bOff + (size_t)k0 * DIM;
    cp16(dB + sb + S2_BH,      Bh + bk);
    cp16(dB + sb + S2_BH + 16, Bh + bk + 8);
    cp16(dB + sb + S2_BL,      Bl + bk);
    cp16(dB + sb + S2_BL + 16, Bl + bk + 8);
  };

#pragma unroll
  for (int s = 0; s < NSTG - 1; s++) {
    fill(s, s);
    asm volatile("cp.async.commit_group;" ::: "memory");
  }

  for (int c = 0; c < NCHUNK; c++) {
    // stage (c+2)%3 was consumed in iteration c-1; barrier makes that visible
    __syncthreads();
    if (c + NSTG - 1 < NCHUNK) fill((c + NSTG - 1) % NSTG, c + NSTG - 1);
    asm volatile("cp.async.commit_group;" ::: "memory");
    // own group-c copies complete...
    asm volatile("cp.async.wait_group %0;" :: "n"(NSTG - 1) : "memory");
    // ...and all other threads' group-c copies made visible
    __syncthreads();

    const uint32_t stg = smu + (uint32_t)((c % NSTG) * S2_STG);
#pragma unroll
    for (int ks = 0; ks < 2; ks++) {
      uint32_t ah[2][4], al[2][4];
#pragma unroll
      for (int mt = 0; mt < 2; mt++) {
        uint32_t ra = stg + (uint32_t)((wm * 32 + mt * 16 + rsel) * 144 +
                                       ks * 32 + csel * 16);
        LDSM4(ah[mt], ra);
        LDSM4(al[mt], ra + 64);
      }
#pragma unroll
      for (int npp = 0; npp < 2; npp++) {
        const int np0 = npp * 2, np1 = npp * 2 + 1;
        uint32_t rb0 = stg + (uint32_t)((ks * 16 + rsel) * S2_LDB +
                                        (wn * 64 + np0 * 16 + csel * 8) * 2);
        uint32_t rb1 = stg + (uint32_t)((ks * 16 + rsel) * S2_LDB +
                                        (wn * 64 + np1 * 16 + csel * 8) * 2);
        uint32_t bh0[4], bl0[4], bh1[4], bl1[4];
        LDSM4T(bh0, rb0 + S2_BH);
        LDSM4T(bl0, rb0 + S2_BL);
        LDSM4T(bh1, rb1 + S2_BH);
        LDSM4T(bl1, rb1 + S2_BL);
        // term hh
        mma16816(acc[0][np0*2],   ah[0], bh0[0], bh0[1]);
        mma16816(acc[1][np0*2],   ah[1], bh0[0], bh0[1]);
        mma16816(acc[0][np0*2+1], ah[0], bh0[2], bh0[3]);
        mma16816(acc[1][np0*2+1], ah[1], bh0[2], bh0[3]);
        mma16816(acc[0][np1*2],   ah[0], bh1[0], bh1[1]);
        mma16816(acc[1][np1*2],   ah[1], bh1[0], bh1[1]);
        mma16816(acc[0][np1*2+1], ah[0], bh1[2], bh1[3]);
        mma16816(acc[1][np1*2+1], ah[1], bh1[2], bh1[3]);
        // term hl
        mma16816(acc[0][np0*2],   ah[0], bl0[0], bl0[1]);
        mma16816(acc[1][np0*2],   ah[1], bl0[0], bl0[1]);
        mma16816(acc[0][np0*2+1], ah[0], bl0[2], bl0[3]);
        mma16816(acc[1][np0*2+1], ah[1], bl0[2], bl0[3]);
        mma16816(acc[0][np1*2],   ah[0], bl1[0], bl1[1]);
        mma16816(acc[1][np1*2],   ah[1], bl1[0], bl1[1]);
        mma16816(acc[0][np1*2+1], ah[0], bl1[2], bl1[3]);
        mma16816(acc[1][np1*2+1], ah[1], bl1[2], bl1[3]);
        // term lh
        mma16816(acc[0][np0*2],   al[0], bh0[0], bh0[1]);
        mma16816(acc[1][np0*2],   al[1], bh0[0], bh0[1]);
        mma16816(acc[0][np0*2+1], al[0], bh0[2], bh0[3]);
        mma16816(acc[1][np0*2+1], al[1], bh0[2], bh0[3]);
        mma16816(acc[0][np1*2],   al[0], bh1[0], bh1[1]);
        mma16816(acc[1][np1*2],   al[1], bh1[0], bh1[1]);
        mma16816(acc[0][np1*2+1], al[0], bh1[2], bh1[3]);
        mma16816(acc[1][np1*2+1], al[1], bh1[2], bh1[3]);
      }
    }
  }

#pragma unroll
  for (int mt = 0; mt < 2; mt++) {
#pragma unroll
    for (int h = 0; h < 2; h++) {
      const int row = m0 + wm * 32 + mt * 16 + (lane >> 2) + h * 8;
      if (row >= mEnd) continue;
      float* cp = C + (size_t)row * DIM + n0 + wn * 64 + (lane & 3) * 2;
#pragma unroll
      for (int nf = 0; nf < 8; nf++) {
        float2 v = make_float2(acc[mt][nf][h * 2], acc[mt][nf][h * 2 + 1]);
        *reinterpret_cast<float2*>(cp + nf * 8) = v;
      }
    }
  }
}

// ---------------- merged GEMM launches ---------------------------------------
__global__ void __launch_bounds__(256, 2) stage1_kernel() {
  const int n0 = blockIdx.x * 64;
  const int y = blockIdx.y;
  if (y < 16) {
    gemm1_core(g_x_h, g_x_l, g_sg_h, g_sg_l, g_su_h, g_su_l,
               g_Hs_h, g_Hs_l, y * 128, T_TOK, n0, nullptr, 0);
  } else {
    const int ti = y - 16;
    if (ti >= g_ntiles) return;
    const int e = g_tile_e[ti];
    const size_t wo = (size_t)e * SW;
    gemm1_core(g_xs_h, g_xs_l, g_gw_h + wo, g_gw_l + wo, g_uw_h + wo, g_uw_l + wo,
               g_Hr_h, g_Hr_l, g_tile_m[ti], g_off[e + 1], n0, g_perm, 1);
  }
}

__global__ void __launch_bounds__(256, 2) stage2_kernel(float* __restrict__ out) {
  const int n0 = blockIdx.x * 128;
  const int y = blockIdx.y;
  if (y < 16) {
    gemm2_core(g_Hs_h, g_Hs_l, g_sd_h, g_sd_l, out, y * 128, T_TOK, n0);
  } else {
    const int ti = y - 16;
    if (ti >= g_ntiles) return;
    const int e = g_tile_e[ti];
    const size_t wo = (size_t)e * SW;
    gemm2_core(g_Hr_h, g_Hr_l, g_dw_h + wo, g_dw_l + wo, g_R,
               g_tile_m[ti], g_off[e + 1], n0);
  }
}

// ---------------- launch -----------------------------------------------------
extern "C" void kernel_launch(void* const* d_in, const int* in_sizes, int n_in,
                              void* d_out, int out_size) {
  const float* x  = (const float*)d_in[0];
  const float* rw = (const float*)d_in[1];
  const float* gw = (const float*)d_in[2];
  const float* uw = (const float*)d_in[3];
  const float* dw = (const float*)d_in[4];
  const float* sg = (const float*)d_in[5];
  const float* su = (const float*)d_in[6];
  const float* sd = (const float*)d_in[7];
  float* out = (float*)d_out;

  cudaFuncSetAttribute(stage1_kernel, cudaFuncAttributeMaxDynamicSharedMemorySize, S1_SMEM);
  cudaFuncSetAttribute(stage2_kernel, cudaFuncAttributeMaxDynamicSharedMemorySize, S2_SMEM);

  // #1 router, #2 plan, #3 split_all
  router_kernel<<<T_TOK / 8, 256>>>(x, rw);
  plan_kernel<<<1, 256>>>();
  const int splitN = 3 * EW4 + 3 * SW4;
  split_all_kernel<<<(splitN + 255) / 256, 256>>>(
      (const float4*)gw, (const float4*)uw, (const float4*)dw,
      (const float4*)sg, (const float4*)su, (const float4*)sd);

  // #4 stage1 (profiled slot), #5 stage2, #6 scatter-add
  dim3 g1(32, 40);
  dim3 g2(16, 40);
  stage1_kernel<<<g1, 256, S1_SMEM>>>();
  stage2_kernel<<<g2, 256, S2_SMEM>>>(out);
  scatter_add_kernel<<<(T_TOK * DIM / 4) / 256, 256>>>((float4*)out);
}

// round 14
// speedup vs baseline: 1.5244x; 1.0122x over previous
#include <cuda_runtime.h>
#include <math.h>
#include <stdint.h>

#define T_TOK 2048
#define DIM   2048
#define NEXP  8
#define EW    (NEXP * DIM * DIM)
#define SW    (DIM * DIM)
#define EW4   (EW / 4)
#define SW4   (SW / 4)

// ---------------- scratch (device globals) ----------------------------------
__device__ uint16_t g_gw_h[EW], g_gw_l[EW];
__device__ uint16_t g_uw_h[EW], g_uw_l[EW];
__device__ uint16_t g_dw_h[EW], g_dw_l[EW];
__device__ uint16_t g_sg_h[SW], g_sg_l[SW];
__device__ uint16_t g_su_h[SW], g_su_l[SW];
__device__ uint16_t g_sd_h[SW], g_sd_l[SW];
__device__ uint16_t g_x_h [SW], g_x_l [SW];
__device__ uint16_t g_xs_h[SW], g_xs_l[SW];
__device__ uint16_t g_Hs_h[SW], g_Hs_l[SW];
__device__ uint16_t g_Hr_h[SW], g_Hr_l[SW];
__device__ float    g_R[T_TOK * DIM];
__device__ int g_off[NEXP + 1];
__device__ int g_eidx[T_TOK], g_perm[T_TOK];
__device__ int g_tile_e[32], g_tile_m[32], g_ntiles;

// ---------------- helpers ----------------------------------------------------
__device__ __forceinline__ uint32_t smem_u32(const void* p) {
  uint32_t a;
  asm("{ .reg .u64 t; cvta.to.shared.u64 t, %1; cvt.u32.u64 %0, t; }" : "=r"(a) : "l"(p));
  return a;
}
__device__ __forceinline__ void cp16(uint32_t dst, const void* src) {
  asm volatile("cp.async.cg.shared.global [%0], [%1], 16;" :: "r"(dst), "l"(src));
}
__device__ __forceinline__ uint32_t pack_hi(float x, float y) {
  return __byte_perm(__float_as_uint(x), __float_as_uint(y), 0x7632);
}
__device__ __forceinline__ uint32_t pack_lo(float x, float y) {
  float lx = x - __uint_as_float(__float_as_uint(x) & 0xFFFF0000u);
  float ly = y - __uint_as_float(__float_as_uint(y) & 0xFFFF0000u);
  uint32_t r;
  asm("cvt.rn.bf16x2.f32 %0, %1, %2;" : "=r"(r) : "f"(ly), "f"(lx));
  return r;
}
__device__ __forceinline__ void mma16816(float* d, const uint32_t* a,
                                         uint32_t b0, uint32_t b1) {
  asm volatile("mma.sync.aligned.m16n8k16.row.col.f32.bf16.bf16.f32 "
               "{%0,%1,%2,%3}, {%4,%5,%6,%7}, {%8,%9}, {%0,%1,%2,%3};"
               : "+f"(d[0]), "+f"(d[1]), "+f"(d[2]), "+f"(d[3])
               : "r"(a[0]), "r"(a[1]), "r"(a[2]), "r"(a[3]), "r"(b0), "r"(b1));
}
#define LDSM4(r, a)                                                            \
  asm volatile("ldmatrix.sync.aligned.m8n8.x4.shared.b16 {%0,%1,%2,%3}, [%4];" \
    : "=r"((r)[0]), "=r"((r)[1]), "=r"((r)[2]), "=r"((r)[3]) : "r"(a))
#define LDSM4T(r, a)                                                           \
  asm volatile("ldmatrix.sync.aligned.m8n8.x4.trans.shared.b16 {%0,%1,%2,%3}, [%4];" \
    : "=r"((r)[0]), "=r"((r)[1]), "=r"((r)[2]), "=r"((r)[3]) : "r"(a))

// ---------------- setup kernels ----------------------------------------------
__global__ void router_kernel(const float* __restrict__ x,
                              const float* __restrict__ rw) {
  int tok  = (blockIdx.x * blockDim.x + threadIdx.x) >> 5;
  int lane = threadIdx.x & 31;
  if (tok >= T_TOK) return;
  const float* xr = x + (size_t)tok * DIM;
  float acc[NEXP];
#pragma unroll
  for (int e = 0; e < NEXP; e++) acc[e] = 0.f;
  for (int k = lane; k < DIM; k += 32) {
    float xv = xr[k];
    const float4* w4 = reinterpret_cast<const float4*>(rw + (size_t)k * NEXP);
    float4 w0 = w4[0], w1 = w4[1];
    acc[0] = fmaf(xv, w0.x, acc[0]); acc[1] = fmaf(xv, w0.y, acc[1]);
    acc[2] = fmaf(xv, w0.z, acc[2]); acc[3] = fmaf(xv, w0.w, acc[3]);
    acc[4] = fmaf(xv, w1.x, acc[4]); acc[5] = fmaf(xv, w1.y, acc[5]);
    acc[6] = fmaf(xv, w1.z, acc[6]); acc[7] = fmaf(xv, w1.w, acc[7]);
  }
#pragma unroll
  for (int o = 16; o > 0; o >>= 1)
#pragma unroll
    for (int e = 0; e < NEXP; e++)
      acc[e] += __shfl_down_sync(0xffffffffu, acc[e], o);
  float sc = 0.f;
  if (lane == 0) {
    float mx = acc[0]; int im = 0;
#pragma unroll
    for (int e = 1; e < NEXP; e++) if (acc[e] > mx) { mx = acc[e]; im = e; }
    sc = 1.f / (1.f + expf(-mx));
    g_eidx[tok] = im;
  }
  sc = __shfl_sync(0xffffffffu, sc, 0);
  const float4* x4 = reinterpret_cast<const float4*>(xr);
  uint2* xh = reinterpret_cast<uint2*>(g_x_h)  + (size_t)tok * (DIM / 4);
  uint2* xl = reinterpret_cast<uint2*>(g_x_l)  + (size_t)tok * (DIM / 4);
  uint2* sh = reinterpret_cast<uint2*>(g_xs_h) + (size_t)tok * (DIM / 4);
  uint2* sl = reinterpret_cast<uint2*>(g_xs_l) + (size_t)tok * (DIM / 4);
  for (int k = lane; k < DIM / 4; k += 32) {
    float4 v = x4[k];
    uint2 h, l;
    h.x = pack_hi(v.x, v.y); h.y = pack_hi(v.z, v.w);
    l.x = pack_lo(v.x, v.y); l.y = pack_lo(v.z, v.w);
    xh[k] = h; xl[k] = l;
    float4 s = make_float4(v.x * sc, v.y * sc, v.z * sc, v.w * sc);
    h.x = pack_hi(s.x, s.y); h.y = pack_hi(s.z, s.w);
    l.x = pack_lo(s.x, s.y); l.y = pack_lo(s.z, s.w);
    sh[k] = h; sl[k] = l;
  }
}

__global__ void plan_kernel() {
  __shared__ int cnt[NEXP], cur[NEXP];
  int t = threadIdx.x;
  if (t < NEXP) cnt[t] = 0;
  __syncthreads();
  for (int i = t; i < T_TOK; i += 256) atomicAdd(&cnt[g_eidx[i]], 1);
  __syncthreads();
  if (t == 0) {
    int o = 0, nt = 0;
    for (int e = 0; e < NEXP; e++) {
      g_off[e] = o; cur[e] = o;
      int c = cnt[e];
      for (int m = 0; m < c; m += 128) { g_tile_e[nt] = e; g_tile_m[nt] = o + m; nt++; }
      o += c;
    }
    g_off[NEXP] = o;
    g_ntiles = nt;
  }
  __syncthreads();
  for (int i = t; i < T_TOK; i += 256) {
    int e = g_eidx[i];
    int p = atomicAdd(&cur[e], 1);
    g_perm[p] = i;
  }
}

__global__ void split_all_kernel(const float4* __restrict__ gw, const float4* __restrict__ uw,
                                 const float4* __restrict__ dw, const float4* __restrict__ sg,
                                 const float4* __restrict__ su, const float4* __restrict__ sd) {
  int i = blockIdx.x * blockDim.x + threadIdx.x;
  const float4* src; uint2 *hi, *lo; int j;
  if      (i < EW4)            { src = gw; hi = (uint2*)g_gw_h; lo = (uint2*)g_gw_l; j = i; }
  else if (i < 2 * EW4)        { src = uw; hi = (uint2*)g_uw_h; lo = (uint2*)g_uw_l; j = i - EW4; }
  else if (i < 3 * EW4)        { src = dw; hi = (uint2*)g_dw_h; lo = (uint2*)g_dw_l; j = i - 2 * EW4; }
  else if (i < 3 * EW4 + SW4)  { src = sg; hi = (uint2*)g_sg_h; lo = (uint2*)g_sg_l; j = i - 3 * EW4; }
  else if (i < 3 * EW4 + 2 * SW4) { src = su; hi = (uint2*)g_su_h; lo = (uint2*)g_su_l; j = i - 3 * EW4 - SW4; }
  else if (i < 3 * EW4 + 3 * SW4) { src = sd; hi = (uint2*)g_sd_h; lo = (uint2*)g_sd_l; j = i - 3 * EW4 - 2 * SW4; }
  else return;
  float4 v = src[j];
  uint2 h, l;
  h.x = pack_hi(v.x, v.y); h.y = pack_hi(v.z, v.w);
  l.x = pack_lo(v.x, v.y); l.y = pack_lo(v.z, v.w);
  hi[j] = h; lo[j] = l;
}

__global__ void scatter_add_kernel(float4* __restrict__ out) {
  int i = blockIdx.x * blockDim.x + threadIdx.x;
  if (i >= T_TOK * DIM / 4) return;
  int p = i >> 9;
  int j = i & 511;
  int t = g_perm[p];
  const float4* R4 = reinterpret_cast<const float4*>(g_R);
  float4 r = R4[i];
  float4 o = out[(size_t)t * 512 + j];
  o.x += r.x; o.y += r.y; o.z += r.z; o.w += r.w;
  out[(size_t)t * 512 + j] = o;
}

// ---------------- stage1: fused gate/up GEMM, tile 128x64, 3-stage ----------
// FROZEN r8 core + r8 boundary (wait -> sync -> fill -> commit).
#define BK      32
#define NSTG    3
#define S1_LDB  144
#define S1_GH   18432
#define S1_GL   23040
#define S1_UH   27648
#define S1_UL   32256
#define S1_STG  36864
#define S1_SMEM (NSTG * S1_STG)
#define NCHUNK  (DIM / BK)

__device__ __forceinline__ void gemm1_core(
    const uint16_t* __restrict__ Ah, const uint16_t* __restrict__ Al,
    const uint16_t* __restrict__ Gh, const uint16_t* __restrict__ Gl,
    const uint16_t* __restrict__ Uh, const uint16_t* __restrict__ Ul,
    uint16_t* __restrict__ Hh, uint16_t* __restrict__ Hl,
    int m0, int mEnd, int n0, const int* __restrict__ perm, int gather) {
  extern __shared__ char smc[];
  const uint32_t smu = smem_u32(smc);
  const int t = threadIdx.x;
  const int lane = t & 31;
  const int wid  = t >> 5;
  const int wm = wid >> 1;
  const int wn = wid & 1;
  const int rsel = lane & 15;
  const int csel = lane >> 4;

  const int am = t >> 1, ahalf = t & 1;
  const int ga = m0 + am;
  const bool av = ga < mEnd;
  const int arow = gather ? (av ? perm[ga] : 0) : (av ? ga : 0);
  const uint16_t* aSrcH = Ah + (size_t)arow * DIM + ahalf * 16;
  const uint16_t* aSrcL = Al + (size_t)arow * DIM + ahalf * 16;
  const uint32_t dA = smu + (uint32_t)(am * 144 + ahalf * 32);
  const int brow = t >> 3, bseg = t & 7;
  const size_t bOff = (size_t)brow * DIM + n0 + bseg * 8;
  const uint32_t dB = smu + (uint32_t)(brow * S1_LDB + bseg * 16);

  float accG[2][4][4], accU[2][4][4];
#pragma unroll
  for (int i = 0; i < 2; i++)
#pragma unroll
    for (int j = 0; j < 4; j++)
#pragma unroll
      for (int q = 0; q < 4; q++) { accG[i][j][q] = 0.f; accU[i][j][q] = 0.f; }

  auto fill = [&](int st, int c) {
    const int k0 = c * BK;
    const uint32_t sb = (uint32_t)st * S1_STG;
    cp16(dA + sb,      aSrcH + k0);
    cp16(dA + sb + 16, aSrcH + k0 + 8);
    cp16(dA + sb + 64, aSrcL + k0);
    cp16(dA + sb + 80, aSrcL + k0 + 8);
    const size_t bk = bOff + (size_t)k0 * DIM;
    cp16(dB + sb + S1_GH, Gh + bk);
    cp16(dB + sb + S1_GL, Gl + bk);
    cp16(dB + sb + S1_UH, Uh + bk);
    cp16(dB + sb + S1_UL, Ul + bk);
  };

#pragma unroll
  for (int s = 0; s < NSTG - 1; s++) {
    fill(s, s);
    asm volatile("cp.async.commit_group;" ::: "memory");
  }

  for (int c = 0; c < NCHUNK; c++) {
    asm volatile("cp.async.wait_group %0;" :: "n"(NSTG - 2) : "memory");
    __syncthreads();
    if (c + NSTG - 1 < NCHUNK) fill((c + NSTG - 1) % NSTG, c + NSTG - 1);
    asm volatile("cp.async.commit_group;" ::: "memory");

    const uint32_t stg = smu + (uint32_t)((c % NSTG) * S1_STG);
#pragma unroll
    for (int ks = 0; ks < 2; ks++) {
      uint32_t ah[2][4], al[2][4];
#pragma unroll
      for (int mt = 0; mt < 2; mt++) {
        uint32_t ra = stg + (uint32_t)((wm * 32 + mt * 16 + rsel) * 144 +
                                       ks * 32 + csel * 16);
        LDSM4(ah[mt], ra);
        LDSM4(al[mt], ra + 64);
      }
#pragma unroll
      for (int np = 0; np < 2; np++) {
        uint32_t rb = stg + (uint32_t)((ks * 16 + rsel) * S1_LDB +
                                       (wn * 32 + np * 16 + csel * 8) * 2);
        uint32_t gh[4], gl[4], uh[4], ul[4];
        LDSM4T(gh, rb + S1_GH);
        LDSM4T(gl, rb + S1_GL);
        LDSM4T(uh, rb + S1_UH);
        LDSM4T(ul, rb + S1_UL);
        const int f0 = np * 2, f1 = np * 2 + 1;
        // term hh (8 independent accumulators)
        mma16816(accG[0][f0], ah[0], gh[0], gh[1]);
        mma16816(accG[1][f0], ah[1], gh[0], gh[1]);
        mma16816(accG[0][f1], ah[0], gh[2], gh[3]);
        mma16816(accG[1][f1], ah[1], gh[2], gh[3]);
        mma16816(accU[0][f0], ah[0], uh[0], uh[1]);
        mma16816(accU[1][f0], ah[1], uh[0], uh[1]);
        mma16816(accU[0][f1], ah[0], uh[2], uh[3]);
        mma16816(accU[1][f1], ah[1], uh[2], uh[3]);
        // term hl
        mma16816(accG[0][f0], ah[0], gl[0], gl[1]);
        mma16816(accG[1][f0], ah[1], gl[0], gl[1]);
        mma16816(accG[0][f1], ah[0], gl[2], gl[3]);
        mma16816(accG[1][f1], ah[1], gl[2], gl[3]);
        mma16816(accU[0][f0], ah[0], ul[0], ul[1]);
        mma16816(accU[1][f0], ah[1], ul[0], ul[1]);
        mma16816(accU[0][f1], ah[0], ul[2], ul[3]);
        mma16816(accU[1][f1], ah[1], ul[2], ul[3]);
        // term lh
        mma16816(accG[0][f0], al[0], gh[0], gh[1]);
        mma16816(accG[1][f0], al[1], gh[0], gh[1]);
        mma16816(accG[0][f1], al[0], gh[2], gh[3]);
        mma16816(accG[1][f1], al[1], gh[2], gh[3]);
        mma16816(accU[0][f0], al[0], uh[0], uh[1]);
        mma16816(accU[1][f0], al[1], uh[0], uh[1]);
        mma16816(accU[0][f1], al[0], uh[2], uh[3]);
        mma16816(accU[1][f1], al[1], uh[2], uh[3]);
      }
    }
  }

#pragma unroll
  for (int mt = 0; mt < 2; mt++) {
#pragma unroll
    for (int h = 0; h < 2; h++) {
      const int row = m0 + wm * 32 + mt * 16 + (lane >> 2) + h * 8;
      if (row >= mEnd) continue;
      const int colb = n0 + wn * 32 + (lane & 3) * 2;
      uint16_t* hpH = Hh + (size_t)row * DIM + colb;
      uint16_t* hpL = Hl + (size_t)row * DIM + colb;
#pragma unroll
      for (int nf = 0; nf < 4; nf++) {
        float g0 = accG[mt][nf][h * 2],     u0 = accU[mt][nf][h * 2];
        float g1 = accG[mt][nf][h * 2 + 1], u1 = accU[mt][nf][h * 2 + 1];
        float h0 = g0 / (1.f + expf(-g0)) * u0;
        float h1 = g1 / (1.f + expf(-g1)) * u1;
        *reinterpret_cast<uint32_t*>(hpH + nf * 8) = pack_hi(h0, h1);
        *reinterpret_cast<uint32_t*>(hpL + nf * 8) = pack_lo(h0, h1);
      }
    }
  }
}

// ---------------- stage2: down GEMM, tile 128x128, 3-stage (r8 config) -------
#define S2_LDB  272
#define S2_BH   18432
#define S2_BL   27136
#define S2_STG  35840
#define S2_SMEM (NSTG * S2_STG)

__device__ __forceinline__ void gemm2_core(
    const uint16_t* __restrict__ Ah, const uint16_t* __restrict__ Al,
    const uint16_t* __restrict__ Bh, const uint16_t* __restrict__ Bl,
    float* __restrict__ C, int m0, int mEnd, int n0) {
  extern __shared__ char smc[];
  const uint32_t smu = smem_u32(smc);
  const int t = threadIdx.x;
  const int lane = t & 31;
  const int wid  = t >> 5;
  const int wm = wid >> 1;
  const int wn = wid & 1;
  const int rsel = lane & 15;
  const int csel = lane >> 4;

  const int am = t >> 1, ahalf = t & 1;
  const int ga = m0 + am;
  const bool av = ga < mEnd;
  const int arow = av ? ga : 0;
  const uint16_t* aSrcH = Ah + (size_t)arow * DIM + ahalf * 16;
  const uint16_t* aSrcL = Al + (size_t)arow * DIM + ahalf * 16;
  const uint32_t dA = smu + (uint32_t)(am * 144 + ahalf * 32);
  const int brow = t >> 3, bseg = t & 7;
  const size_t bOff = (size_t)brow * DIM + n0 + bseg * 16;
  const uint32_t dB = smu + (uint32_t)(brow * S2_LDB + bseg * 32);

  float acc[2][8][4];
#pragma unroll
  for (int i = 0; i < 2; i++)
#pragma unroll
    for (int j = 0; j < 8; j++)
#pragma unroll
      for (int q = 0; q < 4; q++) acc[i][j][q] = 0.f;

  auto fill = [&](int st, int c) {
    const int k0 = c * BK;
    const uint32_t sb = (uint32_t)st * S2_STG;
    cp16(dA + sb,      aSrcH + k0);
    cp16(dA + sb + 16, aSrcH + k0 + 8);
    cp16(dA + sb + 64, aSrcL + k0);
    cp16(dA + sb + 80, aSrcL + k0 + 8);
    const size_t bk = bOff + (size_t)k0 * DIM;
    cp16(dB + sb + S2_BH,      Bh + bk);
    cp16(dB + sb + S2_BH + 16, Bh + bk + 8);
    cp16(dB + sb + S2_BL,      Bl + bk);
    cp16(dB + sb + S2_BL + 16, Bl + bk + 8);
  };

#pragma unroll
  for (int s = 0; s < NSTG - 1; s++) {
    fill(s, s);
    asm volatile("cp.async.commit_group;" ::: "memory");
  }

  for (int c = 0; c < NCHUNK; c++) {
    asm volatile("cp.async.wait_group %0;" :: "n"(NSTG - 2) : "memory");
    __syncthreads();
    if (c + NSTG - 1 < NCHUNK) fill((c + NSTG - 1) % NSTG, c + NSTG - 1);
    asm volatile("cp.async.commit_group;" ::: "memory");

    const uint32_t stg = smu + (uint32_t)((c % NSTG) * S2_STG);
#pragma unroll
    for (int ks = 0; ks < 2; ks++) {
      uint32_t ah[2][4], al[2][4];
#pragma unroll
      for (int mt = 0; mt < 2; mt++) {
        uint32_t ra = stg + (uint32_t)((wm * 32 + mt * 16 + rsel) * 144 +
                                       ks * 32 + csel * 16);
        LDSM4(ah[mt], ra);
        LDSM4(al[mt], ra + 64);
      }
#pragma unroll
      for (int npp = 0; npp < 2; npp++) {
        const int np0 = npp * 2, np1 = npp * 2 + 1;
        uint32_t rb0 = stg + (uint32_t)((ks * 16 + rsel) * S2_LDB +
                                        (wn * 64 + np0 * 16 + csel * 8) * 2);
        uint32_t rb1 = stg + (uint32_t)((ks * 16 + rsel) * S2_LDB +
                                        (wn * 64 + np1 * 16 + csel * 8) * 2);
        uint32_t bh0[4], bl0[4], bh1[4], bl1[4];
        LDSM4T(bh0, rb0 + S2_BH);
        LDSM4T(bl0, rb0 + S2_BL);
        LDSM4T(bh1, rb1 + S2_BH);
        LDSM4T(bl1, rb1 + S2_BL);
        // term hh
        mma16816(acc[0][np0*2],   ah[0], bh0[0], bh0[1]);
        mma16816(acc[1][np0*2],   ah[1], bh0[0], bh0[1]);
        mma16816(acc[0][np0*2+1], ah[0], bh0[2], bh0[3]);
        mma16816(acc[1][np0*2+1], ah[1], bh0[2], bh0[3]);
        mma16816(acc[0][np1*2],   ah[0], bh1[0], bh1[1]);
        mma16816(acc[1][np1*2],   ah[1], bh1[0], bh1[1]);
        mma16816(acc[0][np1*2+1], ah[0], bh1[2], bh1[3]);
        mma16816(acc[1][np1*2+1], ah[1], bh1[2], bh1[3]);
        // term hl
        mma16816(acc[0][np0*2],   ah[0], bl0[0], bl0[1]);
        mma16816(acc[1][np0*2],   ah[1], bl0[0], bl0[1]);
        mma16816(acc[0][np0*2+1], ah[0], bl0[2], bl0[3]);
        mma16816(acc[1][np0*2+1], ah[1], bl0[2], bl0[3]);
        mma16816(acc[0][np1*2],   ah[0], bl1[0], bl1[1]);
        mma16816(acc[1][np1*2],   ah[1], bl1[0], bl1[1]);
        mma16816(acc[0][np1*2+1], ah[0], bl1[2], bl1[3]);
        mma16816(acc[1][np1*2+1], ah[1], bl1[2], bl1[3]);
        // term lh
        mma16816(acc[0][np0*2],   al[0], bh0[0], bh0[1]);
        mma16816(acc[1][np0*2],   al[1], bh0[0], bh0[1]);
        mma16816(acc[0][np0*2+1], al[0], bh0[2], bh0[3]);
        mma16816(acc[1][np0*2+1], al[1], bh0[2], bh0[3]);
        mma16816(acc[0][np1*2],   al[0], bh1[0], bh1[1]);
        mma16816(acc[1][np1*2],   al[1], bh1[0], bh1[1]);
        mma16816(acc[0][np1*2+1], al[0], bh1[2], bh1[3]);
        mma16816(acc[1][np1*2+1], al[1], bh1[2], bh1[3]);
      }
    }
  }

#pragma unroll
  for (int mt = 0; mt < 2; mt++) {
#pragma unroll
    for (int h = 0; h < 2; h++) {
      const int row = m0 + wm * 32 + mt * 16 + (lane >> 2) + h * 8;
      if (row >= mEnd) continue;
      float* cp = C + (size_t)row * DIM + n0 + wn * 64 + (lane & 3) * 2;
#pragma unroll
      for (int nf = 0; nf < 8; nf++) {
        float2 v = make_float2(acc[mt][nf][h * 2], acc[mt][nf][h * 2 + 1]);
        *reinterpret_cast<float2*>(cp + nf * 8) = v;
      }
    }
  }
}

// ---------------- merged GEMM launches ---------------------------------------
__global__ void __launch_bounds__(256, 2) stage1_kernel() {
  const int n0 = blockIdx.x * 64;
  const int y = blockIdx.y;
  if (y < 16) {
    gemm1_core(g_x_h, g_x_l, g_sg_h, g_sg_l, g_su_h, g_su_l,
               g_Hs_h, g_Hs_l, y * 128, T_TOK, n0, nullptr, 0);
  } else {
    const int ti = y - 16;
    if (ti >= g_ntiles) return;
    const int e = g_tile_e[ti];
    const size_t wo = (size_t)e * SW;
    gemm1_core(g_xs_h, g_xs_l, g_gw_h + wo, g_gw_l + wo, g_uw_h + wo, g_uw_l + wo,
               g_Hr_h, g_Hr_l, g_tile_m[ti], g_off[e + 1], n0, g_perm, 1);
  }
}

__global__ void __launch_bounds__(256, 2) stage2_kernel(float* __restrict__ out) {
  const int n0 = blockIdx.x * 128;
  const int y = blockIdx.y;
  if (y < 16) {
    gemm2_core(g_Hs_h, g_Hs_l, g_sd_h, g_sd_l, out, y * 128, T_TOK, n0);
  } else {
    const int ti = y - 16;
    if (ti >= g_ntiles) return;
    const int e = g_tile_e[ti];
    const size_t wo = (size_t)e * SW;
    gemm2_core(g_Hr_h, g_Hr_l, g_dw_h + wo, g_dw_l + wo, g_R,
               g_tile_m[ti], g_off[e + 1], n0);
  }
}

// ---------------- launch -----------------------------------------------------
extern "C" void kernel_launch(void* const* d_in, const int* in_sizes, int n_in,
                              void* d_out, int out_size) {
  const float* x  = (const float*)d_in[0];
  const float* rw = (const float*)d_in[1];
  const float* gw = (const float*)d_in[2];
  const float* uw = (const float*)d_in[3];
  const float* dw = (const float*)d_in[4];
  const float* sg = (const float*)d_in[5];
  const float* su = (const float*)d_in[6];
  const float* sd = (const float*)d_in[7];
  float* out = (float*)d_out;

  cudaFuncSetAttribute(stage1_kernel, cudaFuncAttributeMaxDynamicSharedMemorySize, S1_SMEM);
  cudaFuncSetAttribute(stage2_kernel, cudaFuncAttributeMaxDynamicSharedMemorySize, S2_SMEM);

  // #1 router, #2 plan, #3 split_all
  router_kernel<<<T_TOK / 8, 256>>>(x, rw);
  plan_kernel<<<1, 256>>>();
  const int splitN = 3 * EW4 + 3 * SW4;
  split_all_kernel<<<(splitN + 255) / 256, 256>>>(
      (const float4*)gw, (const float4*)uw, (const float4*)dw,
      (const float4*)sg, (const float4*)su, (const float4*)sd);

  // #4 stage1 (profiled slot), #5 stage2, #6 scatter-add
  dim3 g1(32, 40);
  dim3 g2(16, 40);
  stage1_kernel<<<g1, 256, S1_SMEM>>>();
  stage2_kernel<<<g2, 256, S2_SMEM>>>(out);
  scatter_add_kernel<<<(T_TOK * DIM / 4) / 256, 256>>>((float4*)out);
}

// round 15
// speedup vs baseline: 1.5581x; 1.0221x over previous
#include <cuda_runtime.h>
#include <math.h>
#include <stdint.h>

#define T_TOK 2048
#define DIM   2048
#define NEXP  8
#define EW    (NEXP * DIM * DIM)
#define SW    (DIM * DIM)
#define EW4   (EW / 4)
#define SW4   (SW / 4)

// ---------------- scratch (device globals) ----------------------------------
__device__ uint16_t g_gw_h[EW], g_gw_l[EW];
__device__ uint16_t g_uw_h[EW], g_uw_l[EW];
__device__ uint16_t g_dw_h[EW], g_dw_l[EW];
__device__ uint16_t g_sg_h[SW], g_sg_l[SW];
__device__ uint16_t g_su_h[SW], g_su_l[SW];
__device__ uint16_t g_sd_h[SW], g_sd_l[SW];
__device__ uint16_t g_x_h [SW], g_x_l [SW];
__device__ uint16_t g_xs_h[SW], g_xs_l[SW];
__device__ uint16_t g_Hs_h[SW], g_Hs_l[SW];
__device__ uint16_t g_Hr_h[SW], g_Hr_l[SW];
__device__ int g_off[NEXP + 1];
__device__ int g_eidx[T_TOK], g_perm[T_TOK];
__device__ int g_tile_e[32], g_tile_m[32], g_ntiles;

// ---------------- helpers ----------------------------------------------------
__device__ __forceinline__ uint32_t smem_u32(const void* p) {
  uint32_t a;
  asm("{ .reg .u64 t; cvta.to.shared.u64 t, %1; cvt.u32.u64 %0, t; }" : "=r"(a) : "l"(p));
  return a;
}
__device__ __forceinline__ void cp16(uint32_t dst, const void* src) {
  asm volatile("cp.async.cg.shared.global [%0], [%1], 16;" :: "r"(dst), "l"(src));
}
__device__ __forceinline__ uint32_t pack_hi(float x, float y) {
  return __byte_perm(__float_as_uint(x), __float_as_uint(y), 0x7632);
}
__device__ __forceinline__ uint32_t pack_lo(float x, float y) {
  float lx = x - __uint_as_float(__float_as_uint(x) & 0xFFFF0000u);
  float ly = y - __uint_as_float(__float_as_uint(y) & 0xFFFF0000u);
  uint32_t r;
  asm("cvt.rn.bf16x2.f32 %0, %1, %2;" : "=r"(r) : "f"(ly), "f"(lx));
  return r;
}
__device__ __forceinline__ void mma16816(float* d, const uint32_t* a,
                                         uint32_t b0, uint32_t b1) {
  asm volatile("mma.sync.aligned.m16n8k16.row.col.f32.bf16.bf16.f32 "
               "{%0,%1,%2,%3}, {%4,%5,%6,%7}, {%8,%9}, {%0,%1,%2,%3};"
               : "+f"(d[0]), "+f"(d[1]), "+f"(d[2]), "+f"(d[3])
               : "r"(a[0]), "r"(a[1]), "r"(a[2]), "r"(a[3]), "r"(b0), "r"(b1));
}
#define LDSM4(r, a)                                                            \
  asm volatile("ldmatrix.sync.aligned.m8n8.x4.shared.b16 {%0,%1,%2,%3}, [%4];" \
    : "=r"((r)[0]), "=r"((r)[1]), "=r"((r)[2]), "=r"((r)[3]) : "r"(a))
#define LDSM4T(r, a)                                                           \
  asm volatile("ldmatrix.sync.aligned.m8n8.x4.trans.shared.b16 {%0,%1,%2,%3}, [%4];" \
    : "=r"((r)[0]), "=r"((r)[1]), "=r"((r)[2]), "=r"((r)[3]) : "r"(a))

// ---------------- setup kernels ----------------------------------------------
__global__ void router_kernel(const float* __restrict__ x,
                              const float* __restrict__ rw) {
  int tok  = (blockIdx.x * blockDim.x + threadIdx.x) >> 5;
  int lane = threadIdx.x & 31;
  if (tok >= T_TOK) return;
  const float* xr = x + (size_t)tok * DIM;
  float acc[NEXP];
#pragma unroll
  for (int e = 0; e < NEXP; e++) acc[e] = 0.f;
  for (int k = lane; k < DIM; k += 32) {
    float xv = xr[k];
    const float4* w4 = reinterpret_cast<const float4*>(rw + (size_t)k * NEXP);
    float4 w0 = w4[0], w1 = w4[1];
    acc[0] = fmaf(xv, w0.x, acc[0]); acc[1] = fmaf(xv, w0.y, acc[1]);
    acc[2] = fmaf(xv, w0.z, acc[2]); acc[3] = fmaf(xv, w0.w, acc[3]);
    acc[4] = fmaf(xv, w1.x, acc[4]); acc[5] = fmaf(xv, w1.y, acc[5]);
    acc[6] = fmaf(xv, w1.z, acc[6]); acc[7] = fmaf(xv, w1.w, acc[7]);
  }
#pragma unroll
  for (int o = 16; o > 0; o >>= 1)
#pragma unroll
    for (int e = 0; e < NEXP; e++)
      acc[e] += __shfl_down_sync(0xffffffffu, acc[e], o);
  float sc = 0.f;
  if (lane == 0) {
    float mx = acc[0]; int im = 0;
#pragma unroll
    for (int e = 1; e < NEXP; e++) if (acc[e] > mx) { mx = acc[e]; im = e; }
    sc = 1.f / (1.f + expf(-mx));
    g_eidx[tok] = im;
  }
  sc = __shfl_sync(0xffffffffu, sc, 0);
  const float4* x4 = reinterpret_cast<const float4*>(xr);
  uint2* xh = reinterpret_cast<uint2*>(g_x_h)  + (size_t)tok * (DIM / 4);
  uint2* xl = reinterpret_cast<uint2*>(g_x_l)  + (size_t)tok * (DIM / 4);
  uint2* sh = reinterpret_cast<uint2*>(g_xs_h) + (size_t)tok * (DIM / 4);
  uint2* sl = reinterpret_cast<uint2*>(g_xs_l) + (size_t)tok * (DIM / 4);
  for (int k = lane; k < DIM / 4; k += 32) {
    float4 v = x4[k];
    uint2 h, l;
    h.x = pack_hi(v.x, v.y); h.y = pack_hi(v.z, v.w);
    l.x = pack_lo(v.x, v.y); l.y = pack_lo(v.z, v.w);
    xh[k] = h; xl[k] = l;
    float4 s = make_float4(v.x * sc, v.y * sc, v.z * sc, v.w * sc);
    h.x = pack_hi(s.x, s.y); h.y = pack_hi(s.z, s.w);
    l.x = pack_lo(s.x, s.y); l.y = pack_lo(s.z, s.w);
    sh[k] = h; sl[k] = l;
  }
}

__global__ void plan_kernel() {
  __shared__ int cnt[NEXP], cur[NEXP];
  int t = threadIdx.x;
  if (t < NEXP) cnt[t] = 0;
  __syncthreads();
  for (int i = t; i < T_TOK; i += 256) atomicAdd(&cnt[g_eidx[i]], 1);
  __syncthreads();
  if (t == 0) {
    int o = 0, nt = 0;
    for (int e = 0; e < NEXP; e++) {
      g_off[e] = o; cur[e] = o;
      int c = cnt[e];
      for (int m = 0; m < c; m += 128) { g_tile_e[nt] = e; g_tile_m[nt] = o + m; nt++; }
      o += c;
    }
    g_off[NEXP] = o;
    g_ntiles = nt;
  }
  __syncthreads();
  for (int i = t; i < T_TOK; i += 256) {
    int e = g_eidx[i];
    int p = atomicAdd(&cur[e], 1);
    g_perm[p] = i;
  }
}

__global__ void split_all_kernel(const float4* __restrict__ gw, const float4* __restrict__ uw,
                                 const float4* __restrict__ dw, const float4* __restrict__ sg,
                                 const float4* __restrict__ su, const float4* __restrict__ sd) {
  int i = blockIdx.x * blockDim.x + threadIdx.x;
  const float4* src; uint2 *hi, *lo; int j;
  if      (i < EW4)            { src = gw; hi = (uint2*)g_gw_h; lo = (uint2*)g_gw_l; j = i; }
  else if (i < 2 * EW4)        { src = uw; hi = (uint2*)g_uw_h; lo = (uint2*)g_uw_l; j = i - EW4; }
  else if (i < 3 * EW4)        { src = dw; hi = (uint2*)g_dw_h; lo = (uint2*)g_dw_l; j = i - 2 * EW4; }
  else if (i < 3 * EW4 + SW4)  { src = sg; hi = (uint2*)g_sg_h; lo = (uint2*)g_sg_l; j = i - 3 * EW4; }
  else if (i < 3 * EW4 + 2 * SW4) { src = su; hi = (uint2*)g_su_h; lo = (uint2*)g_su_l; j = i - 3 * EW4 - SW4; }
  else if (i < 3 * EW4 + 3 * SW4) { src = sd; hi = (uint2*)g_sd_h; lo = (uint2*)g_sd_l; j = i - 3 * EW4 - 2 * SW4; }
  else return;
  float4 v = src[j];
  uint2 h, l;
  h.x = pack_hi(v.x, v.y); h.y = pack_hi(v.z, v.w);
  l.x = pack_lo(v.x, v.y); l.y = pack_lo(v.z, v.w);
  hi[j] = h; lo[j] = l;
}

__global__ void zero_out_kernel(float4* __restrict__ out) {
  int i = blockIdx.x * blockDim.x + threadIdx.x;
  if (i < T_TOK * DIM / 4) out[i] = make_float4(0.f, 0.f, 0.f, 0.f);
}

// ---------------- stage1: fused gate/up GEMM, tile 128x64, 3-stage ----------
// FROZEN r8 core + r8 boundary (wait -> sync -> fill -> commit).
#define BK      32
#define NSTG    3
#define S1_LDB  144
#define S1_GH   18432
#define S1_GL   23040
#define S1_UH   27648
#define S1_UL   32256
#define S1_STG  36864
#define S1_SMEM (NSTG * S1_STG)
#define NCHUNK  (DIM / BK)

__device__ __forceinline__ void gemm1_core(
    const uint16_t* __restrict__ Ah, const uint16_t* __restrict__ Al,
    const uint16_t* __restrict__ Gh, const uint16_t* __restrict__ Gl,
    const uint16_t* __restrict__ Uh, const uint16_t* __restrict__ Ul,
    uint16_t* __restrict__ Hh, uint16_t* __restrict__ Hl,
    int m0, int mEnd, int n0, const int* __restrict__ perm, int gather) {
  extern __shared__ char smc[];
  const uint32_t smu = smem_u32(smc);
  const int t = threadIdx.x;
  const int lane = t & 31;
  const int wid  = t >> 5;
  const int wm = wid >> 1;
  const int wn = wid & 1;
  const int rsel = lane & 15;
  const int csel = lane >> 4;

  const int am = t >> 1, ahalf = t & 1;
  const int ga = m0 + am;
  const bool av = ga < mEnd;
  const int arow = gather ? (av ? perm[ga] : 0) : (av ? ga : 0);
  const uint16_t* aSrcH = Ah + (size_t)arow * DIM + ahalf * 16;
  const uint16_t* aSrcL = Al + (size_t)arow * DIM + ahalf * 16;
  const uint32_t dA = smu + (uint32_t)(am * 144 + ahalf * 32);
  const int brow = t >> 3, bseg = t & 7;
  const size_t bOff = (size_t)brow * DIM + n0 + bseg * 8;
  const uint32_t dB = smu + (uint32_t)(brow * S1_LDB + bseg * 16);

  float accG[2][4][4], accU[2][4][4];
#pragma unroll
  for (int i = 0; i < 2; i++)
#pragma unroll
    for (int j = 0; j < 4; j++)
#pragma unroll
      for (int q = 0; q < 4; q++) { accG[i][j][q] = 0.f; accU[i][j][q] = 0.f; }

  auto fill = [&](int st, int c) {
    const int k0 = c * BK;
    const uint32_t sb = (uint32_t)st * S1_STG;
    cp16(dA + sb,      aSrcH + k0);
    cp16(dA + sb + 16, aSrcH + k0 + 8);
    cp16(dA + sb + 64, aSrcL + k0);
    cp16(dA + sb + 80, aSrcL + k0 + 8);
    const size_t bk = bOff + (size_t)k0 * DIM;
    cp16(dB + sb + S1_GH, Gh + bk);
    cp16(dB + sb + S1_GL, Gl + bk);
    cp16(dB + sb + S1_UH, Uh + bk);
    cp16(dB + sb + S1_UL, Ul + bk);
  };

#pragma unroll
  for (int s = 0; s < NSTG - 1; s++) {
    fill(s, s);
    asm volatile("cp.async.commit_group;" ::: "memory");
  }

  for (int c = 0; c < NCHUNK; c++) {
    asm volatile("cp.async.wait_group %0;" :: "n"(NSTG - 2) : "memory");
    __syncthreads();
    if (c + NSTG - 1 < NCHUNK) fill((c + NSTG - 1) % NSTG, c + NSTG - 1);
    asm volatile("cp.async.commit_group;" ::: "memory");

    const uint32_t stg = smu + (uint32_t)((c % NSTG) * S1_STG);
#pragma unroll
    for (int ks = 0; ks < 2; ks++) {
      uint32_t ah[2][4], al[2][4];
#pragma unroll
      for (int mt = 0; mt < 2; mt++) {
        uint32_t ra = stg + (uint32_t)((wm * 32 + mt * 16 + rsel) * 144 +
                                       ks * 32 + csel * 16);
        LDSM4(ah[mt], ra);
        LDSM4(al[mt], ra + 64);
      }
#pragma unroll
      for (int np = 0; np < 2; np++) {
        uint32_t rb = stg + (uint32_t)((ks * 16 + rsel) * S1_LDB +
                                       (wn * 32 + np * 16 + csel * 8) * 2);
        uint32_t gh[4], gl[4], uh[4], ul[4];
        LDSM4T(gh, rb + S1_GH);
        LDSM4T(gl, rb + S1_GL);
        LDSM4T(uh, rb + S1_UH);
        LDSM4T(ul, rb + S1_UL);
        const int f0 = np * 2, f1 = np * 2 + 1;
        // term hh (8 independent accumulators)
        mma16816(accG[0][f0], ah[0], gh[0], gh[1]);
        mma16816(accG[1][f0], ah[1], gh[0], gh[1]);
        mma16816(accG[0][f1], ah[0], gh[2], gh[3]);
        mma16816(accG[1][f1], ah[1], gh[2], gh[3]);
        mma16816(accU[0][f0], ah[0], uh[0], uh[1]);
        mma16816(accU[1][f0], ah[1], uh[0], uh[1]);
        mma16816(accU[0][f1], ah[0], uh[2], uh[3]);
        mma16816(accU[1][f1], ah[1], uh[2], uh[3]);
        // term hl
        mma16816(accG[0][f0], ah[0], gl[0], gl[1]);
        mma16816(accG[1][f0], ah[1], gl[0], gl[1]);
        mma16816(accG[0][f1], ah[0], gl[2], gl[3]);
        mma16816(accG[1][f1], ah[1], gl[2], gl[3]);
        mma16816(accU[0][f0], ah[0], ul[0], ul[1]);
        mma16816(accU[1][f0], ah[1], ul[0], ul[1]);
        mma16816(accU[0][f1], ah[0], ul[2], ul[3]);
        mma16816(accU[1][f1], ah[1], ul[2], ul[3]);
        // term lh
        mma16816(accG[0][f0], al[0], gh[0], gh[1]);
        mma16816(accG[1][f0], al[1], gh[0], gh[1]);
        mma16816(accG[0][f1], al[0], gh[2], gh[3]);
        mma16816(accG[1][f1], al[1], gh[2], gh[3]);
        mma16816(accU[0][f0], al[0], uh[0], uh[1]);
        mma16816(accU[1][f0], al[1], uh[0], uh[1]);
        mma16816(accU[0][f1], al[0], uh[2], uh[3]);
        mma16816(accU[1][f1], al[1], uh[2], uh[3]);
      }
    }
  }

#pragma unroll
  for (int mt = 0; mt < 2; mt++) {
#pragma unroll
    for (int h = 0; h < 2; h++) {
      const int row = m0 + wm * 32 + mt * 16 + (lane >> 2) + h * 8;
      if (row >= mEnd) continue;
      const int colb = n0 + wn * 32 + (lane & 3) * 2;
      uint16_t* hpH = Hh + (size_t)row * DIM + colb;
      uint16_t* hpL = Hl + (size_t)row * DIM + colb;
#pragma unroll
      for (int nf = 0; nf < 4; nf++) {
        float g0 = accG[mt][nf][h * 2],     u0 = accU[mt][nf][h * 2];
        float g1 = accG[mt][nf][h * 2 + 1], u1 = accU[mt][nf][h * 2 + 1];
        float h0 = g0 / (1.f + expf(-g0)) * u0;
        float h1 = g1 / (1.f + expf(-g1)) * u1;
        *reinterpret_cast<uint32_t*>(hpH + nf * 8) = pack_hi(h0, h1);
        *reinterpret_cast<uint32_t*>(hpL + nf * 8) = pack_lo(h0, h1);
      }
    }
  }
}

// ---------------- stage2: down GEMM, tile 128x128, 3-stage (r8 config) -------
// Epilogue now writes with atomicAdd (out pre-zeroed); routed rows scattered
// via perm directly (g_R + scatter_add pass eliminated).
#define S2_LDB  272
#define S2_BH   18432
#define S2_BL   27136
#define S2_STG  35840
#define S2_SMEM (NSTG * S2_STG)

__device__ __forceinline__ void gemm2_core(
    const uint16_t* __restrict__ Ah, const uint16_t* __restrict__ Al,
    const uint16_t* __restrict__ Bh, const uint16_t* __restrict__ Bl,
    float* __restrict__ C, int m0, int mEnd, int n0,
    const int* __restrict__ perm, int scatter) {
  extern __shared__ char smc[];
  const uint32_t smu = smem_u32(smc);
  const int t = threadIdx.x;
  const int lane = t & 31;
  const int wid  = t >> 5;
  const int wm = wid >> 1;
  const int wn = wid & 1;
  const int rsel = lane & 15;
  const int csel = lane >> 4;

  const int am = t >> 1, ahalf = t & 1;
  const int ga = m0 + am;
  const bool av = ga < mEnd;
  const int arow = av ? ga : 0;
  const uint16_t* aSrcH = Ah + (size_t)arow * DIM + ahalf * 16;
  const uint16_t* aSrcL = Al + (size_t)arow * DIM + ahalf * 16;
  const uint32_t dA = smu + (uint32_t)(am * 144 + ahalf * 32);
  const int brow = t >> 3, bseg = t & 7;
  const size_t bOff = (size_t)brow * DIM + n0 + bseg * 16;
  const uint32_t dB = smu + (uint32_t)(brow * S2_LDB + bseg * 32);

  float acc[2][8][4];
#pragma unroll
  for (int i = 0; i < 2; i++)
#pragma unroll
    for (int j = 0; j < 8; j++)
#pragma unroll
      for (int q = 0; q < 4; q++) acc[i][j][q] = 0.f;

  auto fill = [&](int st, int c) {
    const int k0 = c * BK;
    const uint32_t sb = (uint32_t)st * S2_STG;
    cp16(dA + sb,      aSrcH + k0);
    cp16(dA + sb + 16, aSrcH + k0 + 8);
    cp16(dA + sb + 64, aSrcL + k0);
    cp16(dA + sb + 80, aSrcL + k0 + 8);
    const size_t bk = bOff + (size_t)k0 * DIM;
    cp16(dB + sb + S2_BH,      Bh + bk);
    cp16(dB + sb + S2_BH + 16, Bh + bk + 8);
    cp16(dB + sb + S2_BL,      Bl + bk);
    cp16(dB + sb + S2_BL + 16, Bl + bk + 8);
  };

#pragma unroll
  for (int s = 0; s < NSTG - 1; s++) {
    fill(s, s);
    asm volatile("cp.async.commit_group;" ::: "memory");
  }

  for (int c = 0; c < NCHUNK; c++) {
    asm volatile("cp.async.wait_group %0;" :: "n"(NSTG - 2) : "memory");
    __syncthreads();
    if (c + NSTG - 1 < NCHUNK) fill((c + NSTG - 1) % NSTG, c + NSTG - 1);
    asm volatile("cp.async.commit_group;" ::: "memory");

    const uint32_t stg = smu + (uint32_t)((c % NSTG) * S2_STG);
#pragma unroll
    for (int ks = 0; ks < 2; ks++) {
      uint32_t ah[2][4], al[2][4];
#pragma unroll
      for (int mt = 0; mt < 2; mt++) {
        uint32_t ra = stg + (uint32_t)((wm * 32 + mt * 16 + rsel) * 144 +
                                       ks * 32 + csel * 16);
        LDSM4(ah[mt], ra);
        LDSM4(al[mt], ra + 64);
      }
#pragma unroll
      for (int npp = 0; npp < 2; npp++) {
        const int np0 = npp * 2, np1 = npp * 2 + 1;
        uint32_t rb0 = stg + (uint32_t)((ks * 16 + rsel) * S2_LDB +
                                        (wn * 64 + np0 * 16 + csel * 8) * 2);
        uint32_t rb1 = stg + (uint32_t)((ks * 16 + rsel) * S2_LDB +
                                        (wn * 64 + np1 * 16 + csel * 8) * 2);
        uint32_t bh0[4], bl0[4], bh1[4], bl1[4];
        LDSM4T(bh0, rb0 + S2_BH);
        LDSM4T(bl0, rb0 + S2_BL);
        LDSM4T(bh1, rb1 + S2_BH);
        LDSM4T(bl1, rb1 + S2_BL);
        // term hh
        mma16816(acc[0][np0*2],   ah[0], bh0[0], bh0[1]);
        mma16816(acc[1][np0*2],   ah[1], bh0[0], bh0[1]);
        mma16816(acc[0][np0*2+1], ah[0], bh0[2], bh0[3]);
        mma16816(acc[1][np0*2+1], ah[1], bh0[2], bh0[3]);
        mma16816(acc[0][np1*2],   ah[0], bh1[0], bh1[1]);
        mma16816(acc[1][np1*2],   ah[1], bh1[0], bh1[1]);
        mma16816(acc[0][np1*2+1], ah[0], bh1[2], bh1[3]);
        mma16816(acc[1][np1*2+1], ah[1], bh1[2], bh1[3]);
        // term hl
        mma16816(acc[0][np0*2],   ah[0], bl0[0], bl0[1]);
        mma16816(acc[1][np0*2],   ah[1], bl0[0], bl0[1]);
        mma16816(acc[0][np0*2+1], ah[0], bl0[2], bl0[3]);
        mma16816(acc[1][np0*2+1], ah[1], bl0[2], bl0[3]);
        mma16816(acc[0][np1*2],   ah[0], bl1[0], bl1[1]);
        mma16816(acc[1][np1*2],   ah[1], bl1[0], bl1[1]);
        mma16816(acc[0][np1*2+1], ah[0], bl1[2], bl1[3]);
        mma16816(acc[1][np1*2+1], ah[1], bl1[2], bl1[3]);
        // term lh
        mma16816(acc[0][np0*2],   al[0], bh0[0], bh0[1]);
        mma16816(acc[1][np0*2],   al[1], bh0[0], bh0[1]);
        mma16816(acc[0][np0*2+1], al[0], bh0[2], bh0[3]);
        mma16816(acc[1][np0*2+1], al[1], bh0[2], bh0[3]);
        mma16816(acc[0][np1*2],   al[0], bh1[0], bh1[1]);
        mma16816(acc[1][np1*2],   al[1], bh1[0], bh1[1]);
        mma16816(acc[0][np1*2+1], al[0], bh1[2], bh1[3]);
        mma16816(acc[1][np1*2+1], al[1], bh1[2], bh1[3]);
      }
    }
  }

#pragma unroll
  for (int mt = 0; mt < 2; mt++) {
#pragma unroll
    for (int h = 0; h < 2; h++) {
      const int row = m0 + wm * 32 + mt * 16 + (lane >> 2) + h * 8;
      if (row >= mEnd) continue;
      const int crow = scatter ? perm[row] : row;
      float* cp = C + (size_t)crow * DIM + n0 + wn * 64 + (lane & 3) * 2;
#pragma unroll
      for (int nf = 0; nf < 8; nf++) {
        atomicAdd(cp + nf * 8,     acc[mt][nf][h * 2]);
        atomicAdd(cp + nf * 8 + 1, acc[mt][nf][h * 2 + 1]);
      }
    }
  }
}

// ---------------- merged GEMM launches ---------------------------------------
// Grid order: tile index on x (fast), n0 on y (slow) -> concurrent CTAs share
// the same weight columns (better L2 reuse on the B stream).
__global__ void __launch_bounds__(256, 2) stage1_kernel() {
  const int y = blockIdx.x;
  const int n0 = blockIdx.y * 64;
  if (y < 16) {
    gemm1_core(g_x_h, g_x_l, g_sg_h, g_sg_l, g_su_h, g_su_l,
               g_Hs_h, g_Hs_l, y * 128, T_TOK, n0, nullptr, 0);
  } else {
    const int ti = y - 16;
    if (ti >= g_ntiles) return;
    const int e = g_tile_e[ti];
    const size_t wo = (size_t)e * SW;
    gemm1_core(g_xs_h, g_xs_l, g_gw_h + wo, g_gw_l + wo, g_uw_h + wo, g_uw_l + wo,
               g_Hr_h, g_Hr_l, g_tile_m[ti], g_off[e + 1], n0, g_perm, 1);
  }
}

__global__ void __launch_bounds__(256, 2) stage2_kernel(float* __restrict__ out) {
  const int y = blockIdx.x;
  const int n0 = blockIdx.y * 128;
  if (y < 16) {
    gemm2_core(g_Hs_h, g_Hs_l, g_sd_h, g_sd_l, out, y * 128, T_TOK, n0,
               nullptr, 0);
  } else {
    const int ti = y - 16;
    if (ti >= g_ntiles) return;
    const int e = g_tile_e[ti];
    const size_t wo = (size_t)e * SW;
    gemm2_core(g_Hr_h, g_Hr_l, g_dw_h + wo, g_dw_l + wo, out,
               g_tile_m[ti], g_off[e + 1], n0, g_perm, 1);
  }
}

// ---------------- launch -----------------------------------------------------
extern "C" void kernel_launch(void* const* d_in, const int* in_sizes, int n_in,
                              void* d_out, int out_size) {
  const float* x  = (const float*)d_in[0];
  const float* rw = (const float*)d_in[1];
  const float* gw = (const float*)d_in[2];
  const float* uw = (const float*)d_in[3];
  const float* dw = (const float*)d_in[4];
  const float* sg = (const float*)d_in[5];
  const float* su = (const float*)d_in[6];
  const float* sd = (const float*)d_in[7];
  float* out = (float*)d_out;

  cudaFuncSetAttribute(stage1_kernel, cudaFuncAttributeMaxDynamicSharedMemorySize, S1_SMEM);
  cudaFuncSetAttribute(stage2_kernel, cudaFuncAttributeMaxDynamicSharedMemorySize, S2_SMEM);

  // #1 router, #2 plan, #3 split_all, #4 stage1 (profiled), #5 zero, #6 stage2
  router_kernel<<<T_TOK / 8, 256>>>(x, rw);
  plan_kernel<<<1, 256>>>();
  const int splitN = 3 * EW4 + 3 * SW4;
  split_all_kernel<<<(splitN + 255) / 256, 256>>>(
      (const float4*)gw, (const float4*)uw, (const float4*)dw,
      (const float4*)sg, (const float4*)su, (const float4*)sd);

  dim3 g1(40, 32);
  dim3 g2(40, 16);
  stage1_kernel<<<g1, 256, S1_SMEM>>>();
  zero_out_kernel<<<(T_TOK * DIM / 4 + 255) / 256, 256>>>((float4*)out);
  stage2_kernel<<<g2, 256, S2_SMEM>>>(out);
}